// round 2
// baseline (speedup 1.0000x reference)
#include <cuda_runtime.h>
#include <math.h>

#define S_LEN 2048
#define DM    1024
#define NH    16
#define DH    64
#define DFFN  4096

// ---------------- scratch (static device globals: no allocation) ----------------
__device__ float g_hin [S_LEN*DM];
__device__ float g_q   [S_LEN*DM];
__device__ float g_k   [S_LEN*DM];
__device__ float g_v   [S_LEN*DM];
__device__ float g_kt  [NH*DH*S_LEN];   // (h, d, s)
__device__ float g_attn[S_LEN*DM];
__device__ float g_h   [S_LEN*DM];
__device__ float g_f   [S_LEN*DM];
__device__ float g_g1  [S_LEN*DFFN];
__device__ float g_gate[S_LEN*DFFN];

// ---------------- RMSNorm: one block per row ----------------
__global__ void __launch_bounds__(256) rmsnorm_kernel(const float* __restrict__ x,
                                                      const float* __restrict__ w,
                                                      float* __restrict__ out) {
    int row = blockIdx.x;
    int tid = threadIdx.x;
    const float4* xr = (const float4*)(x + (size_t)row * DM);
    const float4* wr = (const float4*)w;
    float4 v = xr[tid];                        // 256 threads * 4 = 1024 floats
    float s = v.x*v.x + v.y*v.y + v.z*v.z + v.w*v.w;
    __shared__ float red[256];
    red[tid] = s;
    __syncthreads();
    for (int o = 128; o > 0; o >>= 1) {
        if (tid < o) red[tid] += red[tid + o];
        __syncthreads();
    }
    float inv = rsqrtf(red[0] * (1.0f / DM) + 1e-6f);
    float4 wv = wr[tid];
    float4 ov;
    ov.x = v.x * inv * wv.x;
    ov.y = v.y * inv * wv.y;
    ov.z = v.z * inv * wv.z;
    ov.w = v.w * inv * wv.w;
    ((float4*)(out + (size_t)row * DM))[tid] = ov;
}

// ---------------- RoPE (in-place on q and k) ----------------
__global__ void __launch_bounds__(256) rope_kernel(float* __restrict__ q,
                                                   float* __restrict__ k,
                                                   const float* __restrict__ cosp,
                                                   const float* __restrict__ sinp) {
    int pid = blockIdx.x * blockDim.x + threadIdx.x;   // 2 * 2048 * 16 * 32
    int t   = pid >> 20;                               // 0 = q, 1 = k
    int r   = pid & ((1 << 20) - 1);
    int s   = r >> 9;
    int rest= r & 511;
    int h   = rest >> 5;
    int i   = rest & 31;
    float* ptr = (t == 0 ? q : k) + (size_t)s * DM + h * DH + 2 * i;
    float2 eo = *(float2*)ptr;
    float c  = cosp[s * 32 + i];
    float sn = sinp[s * 32 + i];
    float2 o;
    o.x = eo.x * c - eo.y * sn;
    o.y = eo.x * sn + eo.y * c;
    *(float2*)ptr = o;
}

// ---------------- K transpose: (s, h, d) -> (h, d, s) ----------------
__global__ void ktrans_kernel(const float* __restrict__ k, float* __restrict__ kt) {
    __shared__ float tile[32][33];
    int h  = blockIdx.z;
    int s0 = blockIdx.x * 32;
    int d0 = blockIdx.y * 32;
    int tx = threadIdx.x, ty = threadIdx.y;   // (32, 8)
    #pragma unroll
    for (int i = 0; i < 32; i += 8)
        tile[ty + i][tx] = k[(size_t)(s0 + ty + i) * DM + h * DH + d0 + tx];
    __syncthreads();
    #pragma unroll
    for (int i = 0; i < 32; i += 8)
        kt[(size_t)(h * DH + d0 + ty + i) * S_LEN + s0 + tx] = tile[tx][ty + i];
}

// ---------------- Flash attention, 64x64 tiles, fp32, full (no mask) ----------------
__global__ void __launch_bounds__(256) attn_kernel(const float* __restrict__ q,
                                                   const float* __restrict__ kt,
                                                   const float* __restrict__ v,
                                                   float* __restrict__ out) {
    __shared__ float Qs[64 * 64];
    __shared__ float KV[64 * 64];   // shared between K^T tile and V tile
    __shared__ float Ps[64 * 64];
    int tid  = threadIdx.x;
    int ty   = tid >> 4, tx = tid & 15;
    int q0   = blockIdx.x * 64;
    int head = blockIdx.y;

    // load Q tile (rows q0..q0+63, head slice)
    #pragma unroll
    for (int it = 0; it < 4; it++) {
        int f = tid + it * 256;
        int r = f >> 4, c4 = f & 15;
        *(float4*)(Qs + r * 64 + c4 * 4) =
            *(const float4*)(q + (size_t)(q0 + r) * DM + head * DH + c4 * 4);
    }

    float o[4][4];
    float m[4], l[4];
    #pragma unroll
    for (int i = 0; i < 4; i++) {
        m[i] = -1e30f; l[i] = 0.f;
        #pragma unroll
        for (int j = 0; j < 4; j++) o[i][j] = 0.f;
    }

    const float* kth = kt + (size_t)head * DH * S_LEN;

    for (int k0 = 0; k0 < S_LEN; k0 += 64) {
        __syncthreads();   // previous PV done reading KV
        // load K^T tile: KV[d][kk]  (rows contiguous in g_kt -> coalesced, conflict-free)
        #pragma unroll
        for (int it = 0; it < 4; it++) {
            int f = tid + it * 256;
            int d = f >> 4, c4 = f & 15;
            *(float4*)(KV + d * 64 + c4 * 4) =
                *(const float4*)(kth + (size_t)d * S_LEN + k0 + c4 * 4);
        }
        __syncthreads();

        // S = Q K^T (fragment 4x4 per thread)
        float sf[4][4];
        #pragma unroll
        for (int i = 0; i < 4; i++)
            #pragma unroll
            for (int j = 0; j < 4; j++) sf[i][j] = 0.f;

        for (int d = 0; d < 64; d++) {
            float qv[4], kv[4];
            #pragma unroll
            for (int i = 0; i < 4; i++) qv[i] = Qs[(ty * 4 + i) * 64 + d];
            #pragma unroll
            for (int j = 0; j < 4; j++) kv[j] = KV[d * 64 + tx * 4 + j];
            #pragma unroll
            for (int i = 0; i < 4; i++)
                #pragma unroll
                for (int j = 0; j < 4; j++) sf[i][j] += qv[i] * kv[j];
        }

        // online softmax (rows owned by 16-lane groups)
        #pragma unroll
        for (int i = 0; i < 4; i++) {
            #pragma unroll
            for (int j = 0; j < 4; j++) sf[i][j] *= 0.125f;   // 1/sqrt(64)
            float mx = fmaxf(fmaxf(sf[i][0], sf[i][1]), fmaxf(sf[i][2], sf[i][3]));
            #pragma unroll
            for (int off = 8; off > 0; off >>= 1)
                mx = fmaxf(mx, __shfl_xor_sync(0xffffffffu, mx, off, 16));
            float mnew  = fmaxf(m[i], mx);
            float alpha = expf(m[i] - mnew);
            float ssum = 0.f;
            #pragma unroll
            for (int j = 0; j < 4; j++) {
                float p = expf(sf[i][j] - mnew);
                sf[i][j] = p;
                ssum += p;
            }
            #pragma unroll
            for (int off = 8; off > 0; off >>= 1)
                ssum += __shfl_xor_sync(0xffffffffu, ssum, off, 16);
            l[i] = l[i] * alpha + ssum;
            m[i] = mnew;
            #pragma unroll
            for (int j = 0; j < 4; j++) o[i][j] *= alpha;
        }

        // write P fragment
        #pragma unroll
        for (int i = 0; i < 4; i++)
            #pragma unroll
            for (int j = 0; j < 4; j++)
                Ps[(ty * 4 + i) * 64 + tx * 4 + j] = sf[i][j];
        __syncthreads();   // P written; S-phase reads of KV done

        // load V tile: KV[kk][d]
        #pragma unroll
        for (int it = 0; it < 4; it++) {
            int f = tid + it * 256;
            int kk = f >> 4, c4 = f & 15;
            *(float4*)(KV + kk * 64 + c4 * 4) =
                *(const float4*)(v + (size_t)(k0 + kk) * DM + head * DH + c4 * 4);
        }
        __syncthreads();

        // O += P V
        for (int kk = 0; kk < 64; kk++) {
            float pv[4], vv[4];
            #pragma unroll
            for (int i = 0; i < 4; i++) pv[i] = Ps[(ty * 4 + i) * 64 + kk];
            #pragma unroll
            for (int j = 0; j < 4; j++) vv[j] = KV[kk * 64 + tx * 4 + j];
            #pragma unroll
            for (int i = 0; i < 4; i++)
                #pragma unroll
                for (int j = 0; j < 4; j++) o[i][j] += pv[i] * vv[j];
        }
    }

    #pragma unroll
    for (int i = 0; i < 4; i++) {
        float invl = 1.0f / l[i];
        #pragma unroll
        for (int j = 0; j < 4; j++)
            out[(size_t)(q0 + ty * 4 + i) * DM + head * DH + tx * 4 + j] = o[i][j] * invl;
    }
}

// ---------------- generic 128x128x16 fp32 GEMM with epilogue ----------------
// EPI: 0 = none, 1 = add R, 2 = silu(acc), 3 = acc * R
template <int EPI>
__global__ void __launch_bounds__(256) gemm_kernel(const float* __restrict__ A,
                                                   const float* __restrict__ B,
                                                   float* __restrict__ C,
                                                   int M, int N, int K,
                                                   const float* __restrict__ R) {
    __shared__ float As[16][128];   // As[k][m]
    __shared__ float Bs[16][128];   // Bs[k][n]
    int tid = threadIdx.x;
    int tm = tid >> 4, tn = tid & 15;
    int m0 = blockIdx.y * 128, n0 = blockIdx.x * 128;

    float acc[8][8];
    #pragma unroll
    for (int i = 0; i < 8; i++)
        #pragma unroll
        for (int j = 0; j < 8; j++) acc[i][j] = 0.f;

    for (int k0 = 0; k0 < K; k0 += 16) {
        // A tile (128 x 16), stored transposed
        #pragma unroll
        for (int it = 0; it < 2; it++) {
            int f = tid + it * 256;
            int row = f >> 2, c4 = f & 3;
            float4 va = *(const float4*)(A + (size_t)(m0 + row) * K + k0 + c4 * 4);
            As[c4 * 4 + 0][row] = va.x;
            As[c4 * 4 + 1][row] = va.y;
            As[c4 * 4 + 2][row] = va.z;
            As[c4 * 4 + 3][row] = va.w;
        }
        // B tile (16 x 128)
        #pragma unroll
        for (int it = 0; it < 2; it++) {
            int f = tid + it * 256;
            int row = f >> 5, c4 = f & 31;
            *(float4*)(&Bs[row][c4 * 4]) =
                *(const float4*)(B + (size_t)(k0 + row) * N + n0 + c4 * 4);
        }
        __syncthreads();
        #pragma unroll
        for (int kk = 0; kk < 16; kk++) {
            float a[8], b[8];
            #pragma unroll
            for (int i = 0; i < 8; i++) a[i] = As[kk][tm * 8 + i];
            #pragma unroll
            for (int j = 0; j < 8; j++) b[j] = Bs[kk][tn + 16 * j];
            #pragma unroll
            for (int i = 0; i < 8; i++)
                #pragma unroll
                for (int j = 0; j < 8; j++) acc[i][j] += a[i] * b[j];
        }
        __syncthreads();
    }

    #pragma unroll
    for (int i = 0; i < 8; i++) {
        int row = m0 + tm * 8 + i;
        #pragma unroll
        for (int j = 0; j < 8; j++) {
            int col = n0 + tn + 16 * j;
            size_t idx = (size_t)row * N + col;
            float vacc = acc[i][j];
            if (EPI == 1)      vacc += R[idx];
            else if (EPI == 2) vacc = vacc / (1.0f + expf(-vacc));
            else if (EPI == 3) vacc *= R[idx];
            C[idx] = vacc;
        }
    }
}

// ---------------- host launch ----------------
extern "C" void kernel_launch(void* const* d_in, const int* in_sizes, int n_in,
                              void* d_out, int out_size) {
    const float* x    = (const float*)d_in[0];
    const float* cosp = (const float*)d_in[1];
    const float* sinp = (const float*)d_in[2];
    const float* wq   = (const float*)d_in[3];
    const float* wk   = (const float*)d_in[4];
    const float* wv   = (const float*)d_in[5];
    const float* wo   = (const float*)d_in[6];
    const float* w1   = (const float*)d_in[7];
    const float* w2   = (const float*)d_in[8];
    const float* w3   = (const float*)d_in[9];
    const float* anw  = (const float*)d_in[10];
    const float* fnw  = (const float*)d_in[11];

    float *hin, *q, *k, *v, *kt, *attn, *h, *f, *g1, *gate;
    cudaGetSymbolAddress((void**)&hin,  g_hin);
    cudaGetSymbolAddress((void**)&q,    g_q);
    cudaGetSymbolAddress((void**)&k,    g_k);
    cudaGetSymbolAddress((void**)&v,    g_v);
    cudaGetSymbolAddress((void**)&kt,   g_kt);
    cudaGetSymbolAddress((void**)&attn, g_attn);
    cudaGetSymbolAddress((void**)&h,    g_h);
    cudaGetSymbolAddress((void**)&f,    g_f);
    cudaGetSymbolAddress((void**)&g1,   g_g1);
    cudaGetSymbolAddress((void**)&gate, g_gate);

    float* out = (float*)d_out;

    // 1) attn rmsnorm
    rmsnorm_kernel<<<S_LEN, 256>>>(x, anw, hin);
    // 2) QKV projections
    gemm_kernel<0><<<dim3(DM / 128, S_LEN / 128), 256>>>(hin, wq, q, S_LEN, DM, DM, nullptr);
    gemm_kernel<0><<<dim3(DM / 128, S_LEN / 128), 256>>>(hin, wk, k, S_LEN, DM, DM, nullptr);
    gemm_kernel<0><<<dim3(DM / 128, S_LEN / 128), 256>>>(hin, wv, v, S_LEN, DM, DM, nullptr);
    // 3) RoPE on q, k
    rope_kernel<<<(2 * S_LEN * NH * 32) / 256, 256>>>(q, k, cosp, sinp);
    // 4) transpose K per head -> (h, d, s)
    ktrans_kernel<<<dim3(S_LEN / 32, DH / 32, NH), dim3(32, 8)>>>(k, kt);
    // 5) attention
    attn_kernel<<<dim3(S_LEN / 64, NH), 256>>>(q, kt, v, attn);
    // 6) output projection + residual
    gemm_kernel<1><<<dim3(DM / 128, S_LEN / 128), 256>>>(attn, wo, h, S_LEN, DM, DM, x);
    // 7) ffn rmsnorm
    rmsnorm_kernel<<<S_LEN, 256>>>(h, fnw, f);
    // 8) swiglu: g1 = silu(f@w1); gate = g1 * (f@w3)
    gemm_kernel<2><<<dim3(DFFN / 128, S_LEN / 128), 256>>>(f, w1, g1, S_LEN, DFFN, DM, nullptr);
    gemm_kernel<3><<<dim3(DFFN / 128, S_LEN / 128), 256>>>(f, w3, gate, S_LEN, DFFN, DM, g1);
    // 9) down projection + residual -> output
    gemm_kernel<1><<<dim3(DM / 128, S_LEN / 128), 256>>>(gate, w2, out, S_LEN, DM, DFFN, h);
}

// round 5
// speedup vs baseline: 2.2108x; 2.2108x over previous
#include <cuda_runtime.h>
#include <math.h>
#include <stdint.h>

#define S_LEN 2048
#define DM    1024
#define NH    16
#define DH    64
#define DFFN  4096

// ---------------- scratch (static device globals: no allocation) ----------------
__device__ float g_hin [S_LEN*DM];
__device__ float g_q   [S_LEN*DM];
__device__ float g_k   [S_LEN*DM];
__device__ float g_v   [S_LEN*DM];
__device__ float g_kt  [NH*DH*S_LEN];   // (h, d, s)
__device__ float g_attn[S_LEN*DM];
__device__ float g_h   [S_LEN*DM];
__device__ float g_f   [S_LEN*DM];
__device__ float g_g1  [S_LEN*DFFN];
__device__ float g_gate[S_LEN*DFFN];

// ---------------- helpers ----------------
__device__ __forceinline__ float tf32r(float x) {
    uint32_t o;
    asm("cvt.rna.tf32.f32 %0, %1;" : "=r"(o) : "f"(x));
    return __uint_as_float(o);
}

__device__ __forceinline__ void mma_m16n8k8(float* d, const uint32_t* a, const uint32_t* b) {
    asm volatile("mma.sync.aligned.m16n8k8.row.col.f32.tf32.tf32.f32 "
                 "{%0,%1,%2,%3}, {%4,%5,%6,%7}, {%8,%9}, {%0,%1,%2,%3};"
                 : "+f"(d[0]), "+f"(d[1]), "+f"(d[2]), "+f"(d[3])
                 : "r"(a[0]), "r"(a[1]), "r"(a[2]), "r"(a[3]),
                   "r"(b[0]), "r"(b[1]));
}

// fused store of 2 adjacent outputs
template <int EPI>
__device__ __forceinline__ void store2(float* __restrict__ C, const float* __restrict__ R,
                                       size_t idx, float x, float y) {
    if (EPI == 1) {
        float2 r = *(const float2*)(R + idx);
        x += r.x; y += r.y;
    } else if (EPI == 2) {
        x = x / (1.0f + expf(-x));
        y = y / (1.0f + expf(-y));
    } else if (EPI == 3) {
        float2 r = *(const float2*)(R + idx);
        x *= r.x; y *= r.y;
    }
    float2 o; o.x = x; o.y = y;
    *(float2*)(C + idx) = o;
}

// ---------------- tf32 mma.sync GEMM core ----------------
// C[M,N] = A[M,K] @ B[K,N]  (both row-major, native layouts)
// CTA tile 128x128, BK=32, 8 warps (warp tile 64x32)
// EPI: 0 none, 1 +R, 2 silu, 3 *R
#define AS_STRIDE 36
#define BS_STRIDE 136

template <int EPI>
__device__ __forceinline__ void gemm_mma_core(const float* __restrict__ A,
                                              const float* __restrict__ B,
                                              float* __restrict__ C,
                                              int N, int K,
                                              const float* __restrict__ R) {
    __shared__ float As[128 * AS_STRIDE];   // [m][k], pad->conflict-free frag loads
    __shared__ float Bs[32 * BS_STRIDE];    // [k][n]

    const int tid = threadIdx.x;
    const int w = tid >> 5, l = tid & 31;
    const int wm = (w >> 2) * 64;      // warp m-offset (2 m-warps)
    const int wn = (w & 3) * 32;       // warp n-offset (4 n-warps)
    const int gid = l >> 2, tig = l & 3;
    const int m0 = blockIdx.y * 128, n0 = blockIdx.x * 128;

    float acc[4][4][4];
    #pragma unroll
    for (int mi = 0; mi < 4; mi++)
        #pragma unroll
        for (int ni = 0; ni < 4; ni++)
            #pragma unroll
            for (int j = 0; j < 4; j++) acc[mi][ni][j] = 0.f;

    float4 pa[4], pb[4];
    // preload first k-tile into registers
    #pragma unroll
    for (int it = 0; it < 4; it++) {
        int f = tid + it * 256;
        pa[it] = *(const float4*)(A + (size_t)(m0 + (f >> 3)) * K + ((f & 7) << 2));
        pb[it] = *(const float4*)(B + (size_t)(f >> 5) * N + n0 + ((f & 31) << 2));
    }

    const int nkt = K >> 5;
    for (int kt = 0; kt < nkt; kt++) {
        // stage prefetched tile into smem with rna tf32 rounding
        #pragma unroll
        for (int it = 0; it < 4; it++) {
            int f = tid + it * 256;
            float4 va = pa[it];
            va.x = tf32r(va.x); va.y = tf32r(va.y); va.z = tf32r(va.z); va.w = tf32r(va.w);
            *(float4*)(As + (f >> 3) * AS_STRIDE + ((f & 7) << 2)) = va;
            float4 vb = pb[it];
            vb.x = tf32r(vb.x); vb.y = tf32r(vb.y); vb.z = tf32r(vb.z); vb.w = tf32r(vb.w);
            *(float4*)(Bs + (f >> 5) * BS_STRIDE + ((f & 31) << 2)) = vb;
        }
        __syncthreads();

        // issue global loads for next k-tile (overlap with MMA phase)
        if (kt + 1 < nkt) {
            int k0 = (kt + 1) << 5;
            #pragma unroll
            for (int it = 0; it < 4; it++) {
                int f = tid + it * 256;
                pa[it] = *(const float4*)(A + (size_t)(m0 + (f >> 3)) * K + k0 + ((f & 7) << 2));
                pb[it] = *(const float4*)(B + (size_t)(k0 + (f >> 5)) * N + n0 + ((f & 31) << 2));
            }
        }

        // compute: 4 k-steps of 8
        #pragma unroll
        for (int ks = 0; ks < 4; ks++) {
            const int kk = ks * 8;
            uint32_t af[4][4];
            #pragma unroll
            for (int mi = 0; mi < 4; mi++) {
                int r = wm + mi * 16 + gid;
                af[mi][0] = __float_as_uint(As[r * AS_STRIDE + kk + tig]);
                af[mi][1] = __float_as_uint(As[(r + 8) * AS_STRIDE + kk + tig]);
                af[mi][2] = __float_as_uint(As[r * AS_STRIDE + kk + tig + 4]);
                af[mi][3] = __float_as_uint(As[(r + 8) * AS_STRIDE + kk + tig + 4]);
            }
            uint32_t bfr[4][2];
            #pragma unroll
            for (int ni = 0; ni < 4; ni++) {
                int cn = wn + ni * 8 + gid;
                bfr[ni][0] = __float_as_uint(Bs[(kk + tig) * BS_STRIDE + cn]);
                bfr[ni][1] = __float_as_uint(Bs[(kk + tig + 4) * BS_STRIDE + cn]);
            }
            #pragma unroll
            for (int mi = 0; mi < 4; mi++)
                #pragma unroll
                for (int ni = 0; ni < 4; ni++)
                    mma_m16n8k8(acc[mi][ni], af[mi], bfr[ni]);
        }
        __syncthreads();
    }

    // epilogue: direct stores with fused op
    #pragma unroll
    for (int mi = 0; mi < 4; mi++) {
        #pragma unroll
        for (int ni = 0; ni < 4; ni++) {
            int r  = m0 + wm + mi * 16 + gid;
            int cc = n0 + wn + ni * 8 + 2 * tig;
            store2<EPI>(C, R, (size_t)r * N + cc,       acc[mi][ni][0], acc[mi][ni][1]);
            store2<EPI>(C, R, (size_t)(r + 8) * N + cc, acc[mi][ni][2], acc[mi][ni][3]);
        }
    }
}

template <int EPI>
__global__ void __launch_bounds__(256, 2) gemm_mma(const float* __restrict__ A,
                                                   const float* __restrict__ B,
                                                   float* __restrict__ C,
                                                   int N, int K,
                                                   const float* __restrict__ R) {
    gemm_mma_core<EPI>(A, B, C, N, K, R);
}

__global__ void __launch_bounds__(256, 2) gemm_mma_qkv(const float* __restrict__ A,
        const float* __restrict__ bq, const float* __restrict__ bk, const float* __restrict__ bv,
        float* __restrict__ q, float* __restrict__ k, float* __restrict__ v, int N, int K) {
    const float* B = blockIdx.z == 0 ? bq : (blockIdx.z == 1 ? bk : bv);
    float* C       = blockIdx.z == 0 ? q  : (blockIdx.z == 1 ? k  : v);
    gemm_mma_core<0>(A, B, C, N, K, nullptr);
}

// ---------------- RMSNorm ----------------
__global__ void __launch_bounds__(256) rmsnorm_kernel(const float* __restrict__ x,
                                                      const float* __restrict__ w,
                                                      float* __restrict__ out) {
    int row = blockIdx.x;
    int tid = threadIdx.x;
    const float4* xr = (const float4*)(x + (size_t)row * DM);
    const float4* wr = (const float4*)w;
    float4 v = xr[tid];
    float s = v.x*v.x + v.y*v.y + v.z*v.z + v.w*v.w;
    __shared__ float red[256];
    red[tid] = s;
    __syncthreads();
    for (int o = 128; o > 0; o >>= 1) {
        if (tid < o) red[tid] += red[tid + o];
        __syncthreads();
    }
    float inv = rsqrtf(red[0] * (1.0f / DM) + 1e-6f);
    float4 wv = wr[tid];
    float4 ov;
    ov.x = v.x * inv * wv.x;
    ov.y = v.y * inv * wv.y;
    ov.z = v.z * inv * wv.z;
    ov.w = v.w * inv * wv.w;
    ((float4*)(out + (size_t)row * DM))[tid] = ov;
}

// ---------------- RoPE ----------------
__global__ void __launch_bounds__(256) rope_kernel(float* __restrict__ q,
                                                   float* __restrict__ k,
                                                   const float* __restrict__ cosp,
                                                   const float* __restrict__ sinp) {
    int pid = blockIdx.x * blockDim.x + threadIdx.x;
    int t   = pid >> 20;
    int r   = pid & ((1 << 20) - 1);
    int s   = r >> 9;
    int rest= r & 511;
    int h   = rest >> 5;
    int i   = rest & 31;
    float* ptr = (t == 0 ? q : k) + (size_t)s * DM + h * DH + 2 * i;
    float2 eo = *(float2*)ptr;
    float c  = cosp[s * 32 + i];
    float sn = sinp[s * 32 + i];
    float2 o;
    o.x = eo.x * c - eo.y * sn;
    o.y = eo.x * sn + eo.y * c;
    *(float2*)ptr = o;
}

// ---------------- K transpose (s,h,d) -> (h,d,s) ----------------
__global__ void ktrans_kernel(const float* __restrict__ k, float* __restrict__ kt) {
    __shared__ float tile[32][33];
    int h  = blockIdx.z;
    int s0 = blockIdx.x * 32;
    int d0 = blockIdx.y * 32;
    int tx = threadIdx.x, ty = threadIdx.y;
    #pragma unroll
    for (int i = 0; i < 32; i += 8)
        tile[ty + i][tx] = k[(size_t)(s0 + ty + i) * DM + h * DH + d0 + tx];
    __syncthreads();
    #pragma unroll
    for (int i = 0; i < 32; i += 8)
        kt[(size_t)(h * DH + d0 + ty + i) * S_LEN + s0 + tx] = tile[tx][ty + i];
}

// ---------------- Flash attention (SIMT fp32) ----------------
__global__ void __launch_bounds__(256) attn_kernel(const float* __restrict__ q,
                                                   const float* __restrict__ kt,
                                                   const float* __restrict__ v,
                                                   float* __restrict__ out) {
    __shared__ float Qs[64 * 64];
    __shared__ float KV[64 * 64];
    __shared__ float Ps[64 * 64];
    int tid  = threadIdx.x;
    int ty   = tid >> 4, tx = tid & 15;
    int q0   = blockIdx.x * 64;
    int head = blockIdx.y;

    #pragma unroll
    for (int it = 0; it < 4; it++) {
        int f = tid + it * 256;
        int r = f >> 4, c4 = f & 15;
        *(float4*)(Qs + r * 64 + c4 * 4) =
            *(const float4*)(q + (size_t)(q0 + r) * DM + head * DH + c4 * 4);
    }

    float o[4][4];
    float m[4], l[4];
    #pragma unroll
    for (int i = 0; i < 4; i++) {
        m[i] = -1e30f; l[i] = 0.f;
        #pragma unroll
        for (int j = 0; j < 4; j++) o[i][j] = 0.f;
    }

    const float* kth = kt + (size_t)head * DH * S_LEN;

    for (int k0 = 0; k0 < S_LEN; k0 += 64) {
        __syncthreads();
        #pragma unroll
        for (int it = 0; it < 4; it++) {
            int f = tid + it * 256;
            int d = f >> 4, c4 = f & 15;
            *(float4*)(KV + d * 64 + c4 * 4) =
                *(const float4*)(kth + (size_t)d * S_LEN + k0 + c4 * 4);
        }
        __syncthreads();

        float sf[4][4];
        #pragma unroll
        for (int i = 0; i < 4; i++)
            #pragma unroll
            for (int j = 0; j < 4; j++) sf[i][j] = 0.f;

        for (int d = 0; d < 64; d++) {
            float qv[4], kv[4];
            #pragma unroll
            for (int i = 0; i < 4; i++) qv[i] = Qs[(ty * 4 + i) * 64 + d];
            #pragma unroll
            for (int j = 0; j < 4; j++) kv[j] = KV[d * 64 + tx * 4 + j];
            #pragma unroll
            for (int i = 0; i < 4; i++)
                #pragma unroll
                for (int j = 0; j < 4; j++) sf[i][j] += qv[i] * kv[j];
        }

        #pragma unroll
        for (int i = 0; i < 4; i++) {
            #pragma unroll
            for (int j = 0; j < 4; j++) sf[i][j] *= 0.125f;
            float mx = fmaxf(fmaxf(sf[i][0], sf[i][1]), fmaxf(sf[i][2], sf[i][3]));
            #pragma unroll
            for (int off = 8; off > 0; off >>= 1)
                mx = fmaxf(mx, __shfl_xor_sync(0xffffffffu, mx, off, 16));
            float mnew  = fmaxf(m[i], mx);
            float alpha = expf(m[i] - mnew);
            float ssum = 0.f;
            #pragma unroll
            for (int j = 0; j < 4; j++) {
                float p = expf(sf[i][j] - mnew);
                sf[i][j] = p;
                ssum += p;
            }
            #pragma unroll
            for (int off = 8; off > 0; off >>= 1)
                ssum += __shfl_xor_sync(0xffffffffu, ssum, off, 16);
            l[i] = l[i] * alpha + ssum;
            m[i] = mnew;
            #pragma unroll
            for (int j = 0; j < 4; j++) o[i][j] *= alpha;
        }

        #pragma unroll
        for (int i = 0; i < 4; i++)
            #pragma unroll
            for (int j = 0; j < 4; j++)
                Ps[(ty * 4 + i) * 64 + tx * 4 + j] = sf[i][j];
        __syncthreads();

        #pragma unroll
        for (int it = 0; it < 4; it++) {
            int f = tid + it * 256;
            int kk = f >> 4, c4 = f & 15;
            *(float4*)(KV + kk * 64 + c4 * 4) =
                *(const float4*)(v + (size_t)(k0 + kk) * DM + head * DH + c4 * 4);
        }
        __syncthreads();

        for (int kk = 0; kk < 64; kk++) {
            float pv[4], vv[4];
            #pragma unroll
            for (int i = 0; i < 4; i++) pv[i] = Ps[(ty * 4 + i) * 64 + kk];
            #pragma unroll
            for (int j = 0; j < 4; j++) vv[j] = KV[kk * 64 + tx * 4 + j];
            #pragma unroll
            for (int i = 0; i < 4; i++)
                #pragma unroll
                for (int j = 0; j < 4; j++) o[i][j] += pv[i] * vv[j];
        }
    }

    #pragma unroll
    for (int i = 0; i < 4; i++) {
        float invl = 1.0f / l[i];
        #pragma unroll
        for (int j = 0; j < 4; j++)
            out[(size_t)(q0 + ty * 4 + i) * DM + head * DH + tx * 4 + j] = o[i][j] * invl;
    }
}

// ---------------- host launch ----------------
extern "C" void kernel_launch(void* const* d_in, const int* in_sizes, int n_in,
                              void* d_out, int out_size) {
    const float* x    = (const float*)d_in[0];
    const float* cosp = (const float*)d_in[1];
    const float* sinp = (const float*)d_in[2];
    const float* wq   = (const float*)d_in[3];
    const float* wk   = (const float*)d_in[4];
    const float* wv   = (const float*)d_in[5];
    const float* wo   = (const float*)d_in[6];
    const float* w1   = (const float*)d_in[7];
    const float* w2   = (const float*)d_in[8];
    const float* w3   = (const float*)d_in[9];
    const float* anw  = (const float*)d_in[10];
    const float* fnw  = (const float*)d_in[11];

    float *hin, *q, *k, *v, *kt, *attn, *h, *f, *g1, *gate;
    cudaGetSymbolAddress((void**)&hin,  g_hin);
    cudaGetSymbolAddress((void**)&q,    g_q);
    cudaGetSymbolAddress((void**)&k,    g_k);
    cudaGetSymbolAddress((void**)&v,    g_v);
    cudaGetSymbolAddress((void**)&kt,   g_kt);
    cudaGetSymbolAddress((void**)&attn, g_attn);
    cudaGetSymbolAddress((void**)&h,    g_h);
    cudaGetSymbolAddress((void**)&f,    g_f);
    cudaGetSymbolAddress((void**)&g1,   g_g1);
    cudaGetSymbolAddress((void**)&gate, g_gate);

    float* out = (float*)d_out;

    // 1) attn rmsnorm
    rmsnorm_kernel<<<S_LEN, 256>>>(x, anw, hin);
    // 2) fused QKV projections (tf32 mma.sync)
    gemm_mma_qkv<<<dim3(DM / 128, S_LEN / 128, 3), 256>>>(hin, wq, wk, wv, q, k, v, DM, DM);
    // 3) RoPE
    rope_kernel<<<(2 * S_LEN * NH * 32) / 256, 256>>>(q, k, cosp, sinp);
    // 4) K transpose per head
    ktrans_kernel<<<dim3(S_LEN / 32, DH / 32, NH), dim3(32, 8)>>>(k, kt);
    // 5) attention
    attn_kernel<<<dim3(S_LEN / 64, NH), 256>>>(q, kt, v, attn);
    // 6) output projection + residual
    gemm_mma<1><<<dim3(DM / 128, S_LEN / 128), 256>>>(attn, wo, h, DM, DM, x);
    // 7) ffn rmsnorm
    rmsnorm_kernel<<<S_LEN, 256>>>(h, fnw, f);
    // 8) swiglu
    gemm_mma<2><<<dim3(DFFN / 128, S_LEN / 128), 256>>>(f, w1, g1, DFFN, DM, nullptr);
    gemm_mma<3><<<dim3(DFFN / 128, S_LEN / 128), 256>>>(f, w3, gate, DFFN, DM, g1);
    // 9) down projection + residual -> out
    gemm_mma<1><<<dim3(DM / 128, S_LEN / 128), 256>>>(gate, w2, out, DM, DFFN, h);
}

// round 6
// speedup vs baseline: 3.2412x; 1.4661x over previous
#include <cuda_runtime.h>
#include <math.h>
#include <stdint.h>

#define S_LEN 2048
#define DM    1024
#define NH    16
#define DH    64
#define DFFN  4096

// ---------------- scratch (static device globals: no allocation) ----------------
__device__ float g_hin [S_LEN*DM];
__device__ float g_q   [S_LEN*DM];
__device__ float g_k   [S_LEN*DM];
__device__ float g_v   [S_LEN*DM];
__device__ float g_attn[S_LEN*DM];
__device__ float g_h   [S_LEN*DM];
__device__ float g_f   [S_LEN*DM];
__device__ float g_g1  [S_LEN*DFFN];
__device__ float g_gate[S_LEN*DFFN];

// ---------------- helpers ----------------
__device__ __forceinline__ float tf32r(float x) {
    uint32_t o;
    asm("cvt.rna.tf32.f32 %0, %1;" : "=r"(o) : "f"(x));
    return __uint_as_float(o);
}

__device__ __forceinline__ void mma_m16n8k8(float* d, const uint32_t* a, const uint32_t* b) {
    asm volatile("mma.sync.aligned.m16n8k8.row.col.f32.tf32.tf32.f32 "
                 "{%0,%1,%2,%3}, {%4,%5,%6,%7}, {%8,%9}, {%0,%1,%2,%3};"
                 : "+f"(d[0]), "+f"(d[1]), "+f"(d[2]), "+f"(d[3])
                 : "r"(a[0]), "r"(a[1]), "r"(a[2]), "r"(a[3]),
                   "r"(b[0]), "r"(b[1]));
}

// fused store of 2 adjacent outputs
template <int EPI>
__device__ __forceinline__ void store2(float* __restrict__ C, const float* __restrict__ R,
                                       size_t idx, float x, float y) {
    if (EPI == 1) {
        float2 r = *(const float2*)(R + idx);
        x += r.x; y += r.y;
    } else if (EPI == 2) {
        x = x / (1.0f + expf(-x));
        y = y / (1.0f + expf(-y));
    } else if (EPI == 3) {
        float2 r = *(const float2*)(R + idx);
        x *= r.x; y *= r.y;
    }
    float2 o; o.x = x; o.y = y;
    *(float2*)(C + idx) = o;
}

// ---------------- tf32 mma.sync GEMM core (unchanged from R5) ----------------
#define AS_STRIDE 36
#define BS_STRIDE 136

template <int EPI>
__device__ __forceinline__ void gemm_mma_core(const float* __restrict__ A,
                                              const float* __restrict__ B,
                                              float* __restrict__ C,
                                              int N, int K,
                                              const float* __restrict__ R) {
    __shared__ float As[128 * AS_STRIDE];
    __shared__ float Bs[32 * BS_STRIDE];

    const int tid = threadIdx.x;
    const int w = tid >> 5, l = tid & 31;
    const int wm = (w >> 2) * 64;
    const int wn = (w & 3) * 32;
    const int gid = l >> 2, tig = l & 3;
    const int m0 = blockIdx.y * 128, n0 = blockIdx.x * 128;

    float acc[4][4][4];
    #pragma unroll
    for (int mi = 0; mi < 4; mi++)
        #pragma unroll
        for (int ni = 0; ni < 4; ni++)
            #pragma unroll
            for (int j = 0; j < 4; j++) acc[mi][ni][j] = 0.f;

    float4 pa[4], pb[4];
    #pragma unroll
    for (int it = 0; it < 4; it++) {
        int f = tid + it * 256;
        pa[it] = *(const float4*)(A + (size_t)(m0 + (f >> 3)) * K + ((f & 7) << 2));
        pb[it] = *(const float4*)(B + (size_t)(f >> 5) * N + n0 + ((f & 31) << 2));
    }

    const int nkt = K >> 5;
    for (int kt = 0; kt < nkt; kt++) {
        #pragma unroll
        for (int it = 0; it < 4; it++) {
            int f = tid + it * 256;
            float4 va = pa[it];
            va.x = tf32r(va.x); va.y = tf32r(va.y); va.z = tf32r(va.z); va.w = tf32r(va.w);
            *(float4*)(As + (f >> 3) * AS_STRIDE + ((f & 7) << 2)) = va;
            float4 vb = pb[it];
            vb.x = tf32r(vb.x); vb.y = tf32r(vb.y); vb.z = tf32r(vb.z); vb.w = tf32r(vb.w);
            *(float4*)(Bs + (f >> 5) * BS_STRIDE + ((f & 31) << 2)) = vb;
        }
        __syncthreads();

        if (kt + 1 < nkt) {
            int k0 = (kt + 1) << 5;
            #pragma unroll
            for (int it = 0; it < 4; it++) {
                int f = tid + it * 256;
                pa[it] = *(const float4*)(A + (size_t)(m0 + (f >> 3)) * K + k0 + ((f & 7) << 2));
                pb[it] = *(const float4*)(B + (size_t)(k0 + (f >> 5)) * N + n0 + ((f & 31) << 2));
            }
        }

        #pragma unroll
        for (int ks = 0; ks < 4; ks++) {
            const int kk = ks * 8;
            uint32_t af[4][4];
            #pragma unroll
            for (int mi = 0; mi < 4; mi++) {
                int r = wm + mi * 16 + gid;
                af[mi][0] = __float_as_uint(As[r * AS_STRIDE + kk + tig]);
                af[mi][1] = __float_as_uint(As[(r + 8) * AS_STRIDE + kk + tig]);
                af[mi][2] = __float_as_uint(As[r * AS_STRIDE + kk + tig + 4]);
                af[mi][3] = __float_as_uint(As[(r + 8) * AS_STRIDE + kk + tig + 4]);
            }
            uint32_t bfr[4][2];
            #pragma unroll
            for (int ni = 0; ni < 4; ni++) {
                int cn = wn + ni * 8 + gid;
                bfr[ni][0] = __float_as_uint(Bs[(kk + tig) * BS_STRIDE + cn]);
                bfr[ni][1] = __float_as_uint(Bs[(kk + tig + 4) * BS_STRIDE + cn]);
            }
            #pragma unroll
            for (int mi = 0; mi < 4; mi++)
                #pragma unroll
                for (int ni = 0; ni < 4; ni++)
                    mma_m16n8k8(acc[mi][ni], af[mi], bfr[ni]);
        }
        __syncthreads();
    }

    #pragma unroll
    for (int mi = 0; mi < 4; mi++) {
        #pragma unroll
        for (int ni = 0; ni < 4; ni++) {
            int r  = m0 + wm + mi * 16 + gid;
            int cc = n0 + wn + ni * 8 + 2 * tig;
            store2<EPI>(C, R, (size_t)r * N + cc,       acc[mi][ni][0], acc[mi][ni][1]);
            store2<EPI>(C, R, (size_t)(r + 8) * N + cc, acc[mi][ni][2], acc[mi][ni][3]);
        }
    }
}

template <int EPI>
__global__ void __launch_bounds__(256, 2) gemm_mma(const float* __restrict__ A,
                                                   const float* __restrict__ B,
                                                   float* __restrict__ C,
                                                   int N, int K,
                                                   const float* __restrict__ R) {
    gemm_mma_core<EPI>(A, B, C, N, K, R);
}

__global__ void __launch_bounds__(256, 2) gemm_mma_qkv(const float* __restrict__ A,
        const float* __restrict__ bq, const float* __restrict__ bk, const float* __restrict__ bv,
        float* __restrict__ q, float* __restrict__ k, float* __restrict__ v, int N, int K) {
    const float* B = blockIdx.z == 0 ? bq : (blockIdx.z == 1 ? bk : bv);
    float* C       = blockIdx.z == 0 ? q  : (blockIdx.z == 1 ? k  : v);
    gemm_mma_core<0>(A, B, C, N, K, nullptr);
}

// ---------------- RMSNorm ----------------
__global__ void __launch_bounds__(256) rmsnorm_kernel(const float* __restrict__ x,
                                                      const float* __restrict__ w,
                                                      float* __restrict__ out) {
    int row = blockIdx.x;
    int tid = threadIdx.x;
    const float4* xr = (const float4*)(x + (size_t)row * DM);
    const float4* wr = (const float4*)w;
    float4 v = xr[tid];
    float s = v.x*v.x + v.y*v.y + v.z*v.z + v.w*v.w;
    __shared__ float red[256];
    red[tid] = s;
    __syncthreads();
    for (int o = 128; o > 0; o >>= 1) {
        if (tid < o) red[tid] += red[tid + o];
        __syncthreads();
    }
    float inv = rsqrtf(red[0] * (1.0f / DM) + 1e-6f);
    float4 wv = wr[tid];
    float4 ov;
    ov.x = v.x * inv * wv.x;
    ov.y = v.y * inv * wv.y;
    ov.z = v.z * inv * wv.z;
    ov.w = v.w * inv * wv.w;
    ((float4*)(out + (size_t)row * DM))[tid] = ov;
}

// ---------------- RoPE ----------------
__global__ void __launch_bounds__(256) rope_kernel(float* __restrict__ q,
                                                   float* __restrict__ k,
                                                   const float* __restrict__ cosp,
                                                   const float* __restrict__ sinp) {
    int pid = blockIdx.x * blockDim.x + threadIdx.x;
    int t   = pid >> 20;
    int r   = pid & ((1 << 20) - 1);
    int s   = r >> 9;
    int rest= r & 511;
    int h   = rest >> 5;
    int i   = rest & 31;
    float* ptr = (t == 0 ? q : k) + (size_t)s * DM + h * DH + 2 * i;
    float2 eo = *(float2*)ptr;
    float c  = cosp[s * 32 + i];
    float sn = sinp[s * 32 + i];
    float2 o;
    o.x = eo.x * c - eo.y * sn;
    o.y = eo.x * sn + eo.y * c;
    *(float2*)ptr = o;
}

// ---------------- Flash attention on tensor cores (tf32 mma.sync) ----------------
// CTA: 256 q-rows x full head; 8 warps, 32 q-rows each (2 x m16 tiles).
// Key tile: 64. S-layout gift: B col-major(n,k) == K[key][d] native.
#define ATQ 256
#define KS_STRIDE 68   // bank = 4*gid + tig  (conflict-free)
#define VS_STRIDE 72   // bank = 8*tig + gid  (conflict-free)
#define PS_STRIDE 68

__global__ void __launch_bounds__(256, 1) attn_mma_kernel(const float* __restrict__ q,
                                                          const float* __restrict__ k,
                                                          const float* __restrict__ v,
                                                          float* __restrict__ out) {
    extern __shared__ float sm[];
    float* Ps = sm;                              // 256 x 68 (Q staging, then P)
    float* Ks = sm + ATQ * PS_STRIDE;            // 64 x 68
    float* Vs = Ks + 64 * KS_STRIDE;             // 64 x 72

    const int tid = threadIdx.x;
    const int w = tid >> 5, l = tid & 31;
    const int gid = l >> 2, tig = l & 3;
    const int q0 = blockIdx.x * ATQ;
    const int head = blockIdx.y;
    const int hoff = head * DH;

    // stage Q (pre-scaled by 1/sqrt(64), tf32-rounded)
    #pragma unroll
    for (int it = 0; it < 16; it++) {
        int f = tid + it * 256;
        int row = f >> 4, c4 = f & 15;
        float4 v4 = *(const float4*)(q + (size_t)(q0 + row) * DM + hoff + c4 * 4);
        v4.x = tf32r(v4.x * 0.125f); v4.y = tf32r(v4.y * 0.125f);
        v4.z = tf32r(v4.z * 0.125f); v4.w = tf32r(v4.w * 0.125f);
        *(float4*)(Ps + row * PS_STRIDE + c4 * 4) = v4;
    }
    __syncthreads();

    // Q fragments to registers (reused every key tile)
    uint32_t qf[2][8][4];
    #pragma unroll
    for (int mi = 0; mi < 2; mi++) {
        int r = w * 32 + mi * 16 + gid;
        #pragma unroll
        for (int ks = 0; ks < 8; ks++) {
            qf[mi][ks][0] = __float_as_uint(Ps[r * PS_STRIDE + ks * 8 + tig]);
            qf[mi][ks][1] = __float_as_uint(Ps[(r + 8) * PS_STRIDE + ks * 8 + tig]);
            qf[mi][ks][2] = __float_as_uint(Ps[r * PS_STRIDE + ks * 8 + tig + 4]);
            qf[mi][ks][3] = __float_as_uint(Ps[(r + 8) * PS_STRIDE + ks * 8 + tig + 4]);
        }
    }
    __syncthreads();   // Ps now reusable as P staging

    float of[2][8][4];
    float mrow[2][2], lrow[2][2];
    #pragma unroll
    for (int mi = 0; mi < 2; mi++) {
        mrow[mi][0] = -1e30f; mrow[mi][1] = -1e30f;
        lrow[mi][0] = 0.f;    lrow[mi][1] = 0.f;
        #pragma unroll
        for (int ni = 0; ni < 8; ni++)
            #pragma unroll
            for (int j = 0; j < 4; j++) of[mi][ni][j] = 0.f;
    }

    for (int k0 = 0; k0 < S_LEN; k0 += 64) {
        // load K, V tiles (tf32-rounded)
        #pragma unroll
        for (int it = 0; it < 4; it++) {
            int f = tid + it * 256;
            int row = f >> 4, c4 = f & 15;
            float4 kv4 = *(const float4*)(k + (size_t)(k0 + row) * DM + hoff + c4 * 4);
            kv4.x = tf32r(kv4.x); kv4.y = tf32r(kv4.y); kv4.z = tf32r(kv4.z); kv4.w = tf32r(kv4.w);
            *(float4*)(Ks + row * KS_STRIDE + c4 * 4) = kv4;
            float4 vv4 = *(const float4*)(v + (size_t)(k0 + row) * DM + hoff + c4 * 4);
            vv4.x = tf32r(vv4.x); vv4.y = tf32r(vv4.y); vv4.z = tf32r(vv4.z); vv4.w = tf32r(vv4.w);
            *(float4*)(Vs + row * VS_STRIDE + c4 * 4) = vv4;
        }
        __syncthreads();

        #pragma unroll
        for (int mi = 0; mi < 2; mi++) {
            // S = Q K^T fragment (16 x 64)
            float sf[8][4];
            #pragma unroll
            for (int ni = 0; ni < 8; ni++)
                #pragma unroll
                for (int j = 0; j < 4; j++) sf[ni][j] = 0.f;
            #pragma unroll
            for (int ks = 0; ks < 8; ks++) {
                #pragma unroll
                for (int ni = 0; ni < 8; ni++) {
                    uint32_t bfr[2];
                    bfr[0] = __float_as_uint(Ks[(ni * 8 + gid) * KS_STRIDE + ks * 8 + tig]);
                    bfr[1] = __float_as_uint(Ks[(ni * 8 + gid) * KS_STRIDE + ks * 8 + tig + 4]);
                    mma_m16n8k8(sf[ni], qf[mi][ks], bfr);
                }
            }
            // online softmax: rows gid (j=0,1) and gid+8 (j=2,3), stats in 4-lane groups
            float mx0 = -1e30f, mx1 = -1e30f;
            #pragma unroll
            for (int ni = 0; ni < 8; ni++) {
                mx0 = fmaxf(mx0, fmaxf(sf[ni][0], sf[ni][1]));
                mx1 = fmaxf(mx1, fmaxf(sf[ni][2], sf[ni][3]));
            }
            mx0 = fmaxf(mx0, __shfl_xor_sync(0xffffffffu, mx0, 1, 4));
            mx0 = fmaxf(mx0, __shfl_xor_sync(0xffffffffu, mx0, 2, 4));
            mx1 = fmaxf(mx1, __shfl_xor_sync(0xffffffffu, mx1, 1, 4));
            mx1 = fmaxf(mx1, __shfl_xor_sync(0xffffffffu, mx1, 2, 4));
            float mn0 = fmaxf(mrow[mi][0], mx0);
            float mn1 = fmaxf(mrow[mi][1], mx1);
            float a0 = __expf(mrow[mi][0] - mn0);
            float a1 = __expf(mrow[mi][1] - mn1);
            float s0 = 0.f, s1 = 0.f;
            #pragma unroll
            for (int ni = 0; ni < 8; ni++) {
                sf[ni][0] = __expf(sf[ni][0] - mn0);
                sf[ni][1] = __expf(sf[ni][1] - mn0);
                sf[ni][2] = __expf(sf[ni][2] - mn1);
                sf[ni][3] = __expf(sf[ni][3] - mn1);
                s0 += sf[ni][0] + sf[ni][1];
                s1 += sf[ni][2] + sf[ni][3];
            }
            s0 += __shfl_xor_sync(0xffffffffu, s0, 1, 4);
            s0 += __shfl_xor_sync(0xffffffffu, s0, 2, 4);
            s1 += __shfl_xor_sync(0xffffffffu, s1, 1, 4);
            s1 += __shfl_xor_sync(0xffffffffu, s1, 2, 4);
            lrow[mi][0] = lrow[mi][0] * a0 + s0;
            lrow[mi][1] = lrow[mi][1] * a1 + s1;
            mrow[mi][0] = mn0; mrow[mi][1] = mn1;
            #pragma unroll
            for (int ni = 0; ni < 8; ni++) {
                of[mi][ni][0] *= a0; of[mi][ni][1] *= a0;
                of[mi][ni][2] *= a1; of[mi][ni][3] *= a1;
            }
            // stage P into per-warp region (rows w*32 + mi*16 + ...)
            int pr = (w * 32 + mi * 16 + gid) * PS_STRIDE;
            #pragma unroll
            for (int ni = 0; ni < 8; ni++) {
                float2 p0; p0.x = tf32r(sf[ni][0]); p0.y = tf32r(sf[ni][1]);
                *(float2*)(Ps + pr + ni * 8 + tig * 2) = p0;
                float2 p1; p1.x = tf32r(sf[ni][2]); p1.y = tf32r(sf[ni][3]);
                *(float2*)(Ps + pr + 8 * PS_STRIDE + ni * 8 + tig * 2) = p1;
            }
        }
        __syncwarp();

        // O += P V
        #pragma unroll
        for (int ks = 0; ks < 8; ks++) {
            uint32_t pf[2][4];
            #pragma unroll
            for (int mi = 0; mi < 2; mi++) {
                int r = (w * 32 + mi * 16 + gid) * PS_STRIDE;
                pf[mi][0] = __float_as_uint(Ps[r + ks * 8 + tig]);
                pf[mi][1] = __float_as_uint(Ps[r + 8 * PS_STRIDE + ks * 8 + tig]);
                pf[mi][2] = __float_as_uint(Ps[r + ks * 8 + tig + 4]);
                pf[mi][3] = __float_as_uint(Ps[r + 8 * PS_STRIDE + ks * 8 + tig + 4]);
            }
            #pragma unroll
            for (int ni = 0; ni < 8; ni++) {
                uint32_t bfr[2];
                bfr[0] = __float_as_uint(Vs[(ks * 8 + tig) * VS_STRIDE + ni * 8 + gid]);
                bfr[1] = __float_as_uint(Vs[(ks * 8 + tig + 4) * VS_STRIDE + ni * 8 + gid]);
                mma_m16n8k8(of[0][ni], pf[0], bfr);
                mma_m16n8k8(of[1][ni], pf[1], bfr);
            }
        }
        __syncthreads();   // done with Ks/Vs before next tile load
    }

    // epilogue: normalize and store
    #pragma unroll
    for (int mi = 0; mi < 2; mi++) {
        int r = q0 + w * 32 + mi * 16 + gid;
        float i0 = 1.0f / lrow[mi][0];
        float i1 = 1.0f / lrow[mi][1];
        #pragma unroll
        for (int ni = 0; ni < 8; ni++) {
            int cc = hoff + ni * 8 + tig * 2;
            float2 o0; o0.x = of[mi][ni][0] * i0; o0.y = of[mi][ni][1] * i0;
            *(float2*)(out + (size_t)r * DM + cc) = o0;
            float2 o1; o1.x = of[mi][ni][2] * i1; o1.y = of[mi][ni][3] * i1;
            *(float2*)(out + (size_t)(r + 8) * DM + cc) = o1;
        }
    }
}

// ---------------- host launch ----------------
extern "C" void kernel_launch(void* const* d_in, const int* in_sizes, int n_in,
                              void* d_out, int out_size) {
    const float* x    = (const float*)d_in[0];
    const float* cosp = (const float*)d_in[1];
    const float* sinp = (const float*)d_in[2];
    const float* wq   = (const float*)d_in[3];
    const float* wk   = (const float*)d_in[4];
    const float* wv   = (const float*)d_in[5];
    const float* wo   = (const float*)d_in[6];
    const float* w1   = (const float*)d_in[7];
    const float* w2   = (const float*)d_in[8];
    const float* w3   = (const float*)d_in[9];
    const float* anw  = (const float*)d_in[10];
    const float* fnw  = (const float*)d_in[11];

    float *hin, *q, *k, *v, *attn, *h, *f, *g1, *gate;
    cudaGetSymbolAddress((void**)&hin,  g_hin);
    cudaGetSymbolAddress((void**)&q,    g_q);
    cudaGetSymbolAddress((void**)&k,    g_k);
    cudaGetSymbolAddress((void**)&v,    g_v);
    cudaGetSymbolAddress((void**)&attn, g_attn);
    cudaGetSymbolAddress((void**)&h,    g_h);
    cudaGetSymbolAddress((void**)&f,    g_f);
    cudaGetSymbolAddress((void**)&g1,   g_g1);
    cudaGetSymbolAddress((void**)&gate, g_gate);

    float* out = (float*)d_out;

    const int ATTN_SMEM = (ATQ * PS_STRIDE + 64 * KS_STRIDE + 64 * VS_STRIDE) * 4;
    cudaFuncSetAttribute(attn_mma_kernel, cudaFuncAttributeMaxDynamicSharedMemorySize, ATTN_SMEM);

    // 1) attn rmsnorm
    rmsnorm_kernel<<<S_LEN, 256>>>(x, anw, hin);
    // 2) fused QKV projections (tf32 mma.sync)
    gemm_mma_qkv<<<dim3(DM / 128, S_LEN / 128, 3), 256>>>(hin, wq, wk, wv, q, k, v, DM, DM);
    // 3) RoPE
    rope_kernel<<<(2 * S_LEN * NH * 32) / 256, 256>>>(q, k, cosp, sinp);
    // 4) attention (tensor-core flash, single wave)
    attn_mma_kernel<<<dim3(S_LEN / ATQ, NH), 256, ATTN_SMEM>>>(q, k, v, attn);
    // 5) output projection + residual
    gemm_mma<1><<<dim3(DM / 128, S_LEN / 128), 256>>>(attn, wo, h, DM, DM, x);
    // 6) ffn rmsnorm
    rmsnorm_kernel<<<S_LEN, 256>>>(h, fnw, f);
    // 7) swiglu
    gemm_mma<2><<<dim3(DFFN / 128, S_LEN / 128), 256>>>(f, w1, g1, DFFN, DM, nullptr);
    gemm_mma<3><<<dim3(DFFN / 128, S_LEN / 128), 256>>>(f, w3, gate, DFFN, DM, g1);
    // 8) down projection + residual -> out
    gemm_mma<1><<<dim3(DM / 128, S_LEN / 128), 256>>>(gate, w2, out, DM, DFFN, h);
}

// round 9
// speedup vs baseline: 4.0307x; 1.2436x over previous
#include <cuda_runtime.h>
#include <cuda_fp16.h>
#include <math.h>
#include <stdint.h>

#define S_LEN 2048
#define DM    1024
#define NH    16
#define DH    64
#define DFFN  4096

// ---------------- scratch (static device globals: no allocation) ----------------
__device__ float g_hin [S_LEN*DM];
__device__ float g_q   [S_LEN*DM];
__device__ float g_k   [S_LEN*DM];
__device__ float g_v   [S_LEN*DM];
__device__ float g_attn[S_LEN*DM];
__device__ float g_h   [S_LEN*DM];
__device__ float g_f   [S_LEN*DM];
__device__ float g_g1  [S_LEN*DFFN];
__device__ float g_gate[S_LEN*DFFN];

// ---------------- helpers ----------------
__device__ __forceinline__ float tf32r(float x) {
    uint32_t o;
    asm("cvt.rna.tf32.f32 %0, %1;" : "=r"(o) : "f"(x));
    return __uint_as_float(o);
}

__device__ __forceinline__ void mma_m16n8k8(float* d, const uint32_t* a, const uint32_t* b) {
    asm volatile("mma.sync.aligned.m16n8k8.row.col.f32.tf32.tf32.f32 "
                 "{%0,%1,%2,%3}, {%4,%5,%6,%7}, {%8,%9}, {%0,%1,%2,%3};"
                 : "+f"(d[0]), "+f"(d[1]), "+f"(d[2]), "+f"(d[3])
                 : "r"(a[0]), "r"(a[1]), "r"(a[2]), "r"(a[3]),
                   "r"(b[0]), "r"(b[1]));
}

__device__ __forceinline__ void mma_m16n8k16h(float* d, const uint32_t* a, const uint32_t* b) {
    asm volatile("mma.sync.aligned.m16n8k16.row.col.f32.f16.f16.f32 "
                 "{%0,%1,%2,%3}, {%4,%5,%6,%7}, {%8,%9}, {%0,%1,%2,%3};"
                 : "+f"(d[0]), "+f"(d[1]), "+f"(d[2]), "+f"(d[3])
                 : "r"(a[0]), "r"(a[1]), "r"(a[2]), "r"(a[3]),
                   "r"(b[0]), "r"(b[1]));
}

__device__ __forceinline__ uint2 f4_to_h4(float4 v) {
    __half2 a = __floats2half2_rn(v.x, v.y);
    __half2 b = __floats2half2_rn(v.z, v.w);
    uint2 r;
    r.x = *(uint32_t*)&a;
    r.y = *(uint32_t*)&b;
    return r;
}

// fused store of 2 adjacent outputs
template <int EPI>
__device__ __forceinline__ void store2(float* __restrict__ C, const float* __restrict__ R,
                                       size_t idx, float x, float y) {
    if (EPI == 1) {
        float2 r = *(const float2*)(R + idx);
        x += r.x; y += r.y;
    } else if (EPI == 2) {
        x = x / (1.0f + expf(-x));
        y = y / (1.0f + expf(-y));
    } else if (EPI == 3) {
        float2 r = *(const float2*)(R + idx);
        x *= r.x; y *= r.y;
    }
    float2 o; o.x = x; o.y = y;
    *(float2*)(C + idx) = o;
}

// ---------------- fp16 m16n8k16 GEMM core ----------------
// C[M,N] = A[M,K] @ B[K,N]  (row-major inputs), CTA tile 128x128, BK=32.
// A staged [m][k] halves, B staged [n][k] halves (transpose-on-store).
// Strides 40 halves (20 words) -> frag loads conflict-free (20*gid+tig permutation).
#define HS 40

template <int EPI>
__device__ __forceinline__ void gemm_mma_core(const float* __restrict__ A,
                                              const float* __restrict__ B,
                                              float* __restrict__ C,
                                              int N, int K,
                                              const float* __restrict__ R) {
    __shared__ __half As[128 * HS];   // [m][k]
    __shared__ __half Bs[128 * HS];   // [n][k]

    const int tid = threadIdx.x;
    const int w = tid >> 5, l = tid & 31;
    const int wm = (w >> 2) * 64;
    const int wn = (w & 3) * 32;
    const int gid = l >> 2, tig = l & 3;
    const int m0 = blockIdx.y * 128, n0 = blockIdx.x * 128;

    float acc[4][4][4];
    #pragma unroll
    for (int mi = 0; mi < 4; mi++)
        #pragma unroll
        for (int ni = 0; ni < 4; ni++)
            #pragma unroll
            for (int j = 0; j < 4; j++) acc[mi][ni][j] = 0.f;

    float4 pa[4];
    float  pb[4][4];
    // preload first k-tile
    #pragma unroll
    for (int it = 0; it < 4; it++) {
        int f = tid + it * 256;
        pa[it] = *(const float4*)(A + (size_t)(m0 + (f >> 3)) * K + ((f & 7) << 2));
        int n = f & 127, kb = f >> 7;   // kb in 0..7 -> k = 4*kb
        #pragma unroll
        for (int j = 0; j < 4; j++)
            pb[it][j] = B[(size_t)(4 * kb + j) * N + n0 + n];
    }

    const int nkt = K >> 5;
    for (int kt = 0; kt < nkt; kt++) {
        // stage into smem as halves
        #pragma unroll
        for (int it = 0; it < 4; it++) {
            int f = tid + it * 256;
            int row = f >> 3, c4 = f & 7;
            *(uint2*)(As + row * HS + c4 * 4) = f4_to_h4(pa[it]);
            int n = f & 127, kb = f >> 7;
            float4 bv; bv.x = pb[it][0]; bv.y = pb[it][1]; bv.z = pb[it][2]; bv.w = pb[it][3];
            *(uint2*)(Bs + n * HS + kb * 4) = f4_to_h4(bv);
        }
        __syncthreads();

        // prefetch next k-tile
        if (kt + 1 < nkt) {
            int k0 = (kt + 1) << 5;
            #pragma unroll
            for (int it = 0; it < 4; it++) {
                int f = tid + it * 256;
                pa[it] = *(const float4*)(A + (size_t)(m0 + (f >> 3)) * K + k0 + ((f & 7) << 2));
                int n = f & 127, kb = f >> 7;
                #pragma unroll
                for (int j = 0; j < 4; j++)
                    pb[it][j] = B[(size_t)(k0 + 4 * kb + j) * N + n0 + n];
            }
        }

        // compute: 2 k-steps of 16
        #pragma unroll
        for (int ks = 0; ks < 2; ks++) {
            const int bk = ks * 16 + 2 * tig;
            uint32_t af[4][4];
            #pragma unroll
            for (int mi = 0; mi < 4; mi++) {
                int r = wm + mi * 16 + gid;
                af[mi][0] = *(const uint32_t*)(As + r * HS + bk);
                af[mi][1] = *(const uint32_t*)(As + (r + 8) * HS + bk);
                af[mi][2] = *(const uint32_t*)(As + r * HS + bk + 8);
                af[mi][3] = *(const uint32_t*)(As + (r + 8) * HS + bk + 8);
            }
            uint32_t bfr[4][2];
            #pragma unroll
            for (int ni = 0; ni < 4; ni++) {
                int cn = wn + ni * 8 + gid;
                bfr[ni][0] = *(const uint32_t*)(Bs + cn * HS + bk);
                bfr[ni][1] = *(const uint32_t*)(Bs + cn * HS + bk + 8);
            }
            #pragma unroll
            for (int mi = 0; mi < 4; mi++)
                #pragma unroll
                for (int ni = 0; ni < 4; ni++)
                    mma_m16n8k16h(acc[mi][ni], af[mi], bfr[ni]);
        }
        __syncthreads();
    }

    #pragma unroll
    for (int mi = 0; mi < 4; mi++) {
        #pragma unroll
        for (int ni = 0; ni < 4; ni++) {
            int r  = m0 + wm + mi * 16 + gid;
            int cc = n0 + wn + ni * 8 + 2 * tig;
            store2<EPI>(C, R, (size_t)r * N + cc,       acc[mi][ni][0], acc[mi][ni][1]);
            store2<EPI>(C, R, (size_t)(r + 8) * N + cc, acc[mi][ni][2], acc[mi][ni][3]);
        }
    }
}

template <int EPI>
__global__ void __launch_bounds__(256, 2) gemm_mma(const float* __restrict__ A,
                                                   const float* __restrict__ B,
                                                   float* __restrict__ C,
                                                   int N, int K,
                                                   const float* __restrict__ R) {
    gemm_mma_core<EPI>(A, B, C, N, K, R);
}

__global__ void __launch_bounds__(256, 2) gemm_mma_qkv(const float* __restrict__ A,
        const float* __restrict__ bq, const float* __restrict__ bk, const float* __restrict__ bv,
        float* __restrict__ q, float* __restrict__ k, float* __restrict__ v, int N, int K) {
    const float* B = blockIdx.z == 0 ? bq : (blockIdx.z == 1 ? bk : bv);
    float* C       = blockIdx.z == 0 ? q  : (blockIdx.z == 1 ? k  : v);
    gemm_mma_core<0>(A, B, C, N, K, nullptr);
}

// ---------------- RMSNorm ----------------
__global__ void __launch_bounds__(256) rmsnorm_kernel(const float* __restrict__ x,
                                                      const float* __restrict__ w,
                                                      float* __restrict__ out) {
    int row = blockIdx.x;
    int tid = threadIdx.x;
    const float4* xr = (const float4*)(x + (size_t)row * DM);
    const float4* wr = (const float4*)w;
    float4 v = xr[tid];
    float s = v.x*v.x + v.y*v.y + v.z*v.z + v.w*v.w;
    __shared__ float red[256];
    red[tid] = s;
    __syncthreads();
    for (int o = 128; o > 0; o >>= 1) {
        if (tid < o) red[tid] += red[tid + o];
        __syncthreads();
    }
    float inv = rsqrtf(red[0] * (1.0f / DM) + 1e-6f);
    float4 wv = wr[tid];
    float4 ov;
    ov.x = v.x * inv * wv.x;
    ov.y = v.y * inv * wv.y;
    ov.z = v.z * inv * wv.z;
    ov.w = v.w * inv * wv.w;
    ((float4*)(out + (size_t)row * DM))[tid] = ov;
}

// ---------------- RoPE ----------------
__global__ void __launch_bounds__(256) rope_kernel(float* __restrict__ q,
                                                   float* __restrict__ k,
                                                   const float* __restrict__ cosp,
                                                   const float* __restrict__ sinp) {
    int pid = blockIdx.x * blockDim.x + threadIdx.x;
    int t   = pid >> 20;
    int r   = pid & ((1 << 20) - 1);
    int s   = r >> 9;
    int rest= r & 511;
    int h   = rest >> 5;
    int i   = rest & 31;
    float* ptr = (t == 0 ? q : k) + (size_t)s * DM + h * DH + 2 * i;
    float2 eo = *(float2*)ptr;
    float c  = cosp[s * 32 + i];
    float sn = sinp[s * 32 + i];
    float2 o;
    o.x = eo.x * c - eo.y * sn;
    o.y = eo.x * sn + eo.y * c;
    *(float2*)ptr = o;
}

// ---------------- Flash attention on tensor cores (tf32 mma.sync, from R6) ----------------
#define ATQ 256
#define KS_STRIDE 68
#define VS_STRIDE 72
#define PS_STRIDE 68

__global__ void __launch_bounds__(256, 1) attn_mma_kernel(const float* __restrict__ q,
                                                          const float* __restrict__ k,
                                                          const float* __restrict__ v,
                                                          float* __restrict__ out) {
    extern __shared__ float sm[];
    float* Ps = sm;
    float* Ks = sm + ATQ * PS_STRIDE;
    float* Vs = Ks + 64 * KS_STRIDE;

    const int tid = threadIdx.x;
    const int w = tid >> 5, l = tid & 31;
    const int gid = l >> 2, tig = l & 3;
    const int q0 = blockIdx.x * ATQ;
    const int head = blockIdx.y;
    const int hoff = head * DH;

    #pragma unroll
    for (int it = 0; it < 16; it++) {
        int f = tid + it * 256;
        int row = f >> 4, c4 = f & 15;
        float4 v4 = *(const float4*)(q + (size_t)(q0 + row) * DM + hoff + c4 * 4);
        v4.x = tf32r(v4.x * 0.125f); v4.y = tf32r(v4.y * 0.125f);
        v4.z = tf32r(v4.z * 0.125f); v4.w = tf32r(v4.w * 0.125f);
        *(float4*)(Ps + row * PS_STRIDE + c4 * 4) = v4;
    }
    __syncthreads();

    uint32_t qf[2][8][4];
    #pragma unroll
    for (int mi = 0; mi < 2; mi++) {
        int r = w * 32 + mi * 16 + gid;
        #pragma unroll
        for (int ks = 0; ks < 8; ks++) {
            qf[mi][ks][0] = __float_as_uint(Ps[r * PS_STRIDE + ks * 8 + tig]);
            qf[mi][ks][1] = __float_as_uint(Ps[(r + 8) * PS_STRIDE + ks * 8 + tig]);
            qf[mi][ks][2] = __float_as_uint(Ps[r * PS_STRIDE + ks * 8 + tig + 4]);
            qf[mi][ks][3] = __float_as_uint(Ps[(r + 8) * PS_STRIDE + ks * 8 + tig + 4]);
        }
    }
    __syncthreads();

    float of[2][8][4];
    float mrow[2][2], lrow[2][2];
    #pragma unroll
    for (int mi = 0; mi < 2; mi++) {
        mrow[mi][0] = -1e30f; mrow[mi][1] = -1e30f;
        lrow[mi][0] = 0.f;    lrow[mi][1] = 0.f;
        #pragma unroll
        for (int ni = 0; ni < 8; ni++)
            #pragma unroll
            for (int j = 0; j < 4; j++) of[mi][ni][j] = 0.f;
    }

    for (int k0 = 0; k0 < S_LEN; k0 += 64) {
        #pragma unroll
        for (int it = 0; it < 4; it++) {
            int f = tid + it * 256;
            int row = f >> 4, c4 = f & 15;
            float4 kv4 = *(const float4*)(k + (size_t)(k0 + row) * DM + hoff + c4 * 4);
            kv4.x = tf32r(kv4.x); kv4.y = tf32r(kv4.y); kv4.z = tf32r(kv4.z); kv4.w = tf32r(kv4.w);
            *(float4*)(Ks + row * KS_STRIDE + c4 * 4) = kv4;
            float4 vv4 = *(const float4*)(v + (size_t)(k0 + row) * DM + hoff + c4 * 4);
            vv4.x = tf32r(vv4.x); vv4.y = tf32r(vv4.y); vv4.z = tf32r(vv4.z); vv4.w = tf32r(vv4.w);
            *(float4*)(Vs + row * VS_STRIDE + c4 * 4) = vv4;
        }
        __syncthreads();

        #pragma unroll
        for (int mi = 0; mi < 2; mi++) {
            float sf[8][4];
            #pragma unroll
            for (int ni = 0; ni < 8; ni++)
                #pragma unroll
                for (int j = 0; j < 4; j++) sf[ni][j] = 0.f;
            #pragma unroll
            for (int ks = 0; ks < 8; ks++) {
                #pragma unroll
                for (int ni = 0; ni < 8; ni++) {
                    uint32_t bfr[2];
                    bfr[0] = __float_as_uint(Ks[(ni * 8 + gid) * KS_STRIDE + ks * 8 + tig]);
                    bfr[1] = __float_as_uint(Ks[(ni * 8 + gid) * KS_STRIDE + ks * 8 + tig + 4]);
                    mma_m16n8k8(sf[ni], qf[mi][ks], bfr);
                }
            }
            float mx0 = -1e30f, mx1 = -1e30f;
            #pragma unroll
            for (int ni = 0; ni < 8; ni++) {
                mx0 = fmaxf(mx0, fmaxf(sf[ni][0], sf[ni][1]));
                mx1 = fmaxf(mx1, fmaxf(sf[ni][2], sf[ni][3]));
            }
            mx0 = fmaxf(mx0, __shfl_xor_sync(0xffffffffu, mx0, 1, 4));
            mx0 = fmaxf(mx0, __shfl_xor_sync(0xffffffffu, mx0, 2, 4));
            mx1 = fmaxf(mx1, __shfl_xor_sync(0xffffffffu, mx1, 1, 4));
            mx1 = fmaxf(mx1, __shfl_xor_sync(0xffffffffu, mx1, 2, 4));
            float mn0 = fmaxf(mrow[mi][0], mx0);
            float mn1 = fmaxf(mrow[mi][1], mx1);
            float a0 = __expf(mrow[mi][0] - mn0);
            float a1 = __expf(mrow[mi][1] - mn1);
            float s0 = 0.f, s1 = 0.f;
            #pragma unroll
            for (int ni = 0; ni < 8; ni++) {
                sf[ni][0] = __expf(sf[ni][0] - mn0);
                sf[ni][1] = __expf(sf[ni][1] - mn0);
                sf[ni][2] = __expf(sf[ni][2] - mn1);
                sf[ni][3] = __expf(sf[ni][3] - mn1);
                s0 += sf[ni][0] + sf[ni][1];
                s1 += sf[ni][2] + sf[ni][3];
            }
            s0 += __shfl_xor_sync(0xffffffffu, s0, 1, 4);
            s0 += __shfl_xor_sync(0xffffffffu, s0, 2, 4);
            s1 += __shfl_xor_sync(0xffffffffu, s1, 1, 4);
            s1 += __shfl_xor_sync(0xffffffffu, s1, 2, 4);
            lrow[mi][0] = lrow[mi][0] * a0 + s0;
            lrow[mi][1] = lrow[mi][1] * a1 + s1;
            mrow[mi][0] = mn0; mrow[mi][1] = mn1;
            #pragma unroll
            for (int ni = 0; ni < 8; ni++) {
                of[mi][ni][0] *= a0; of[mi][ni][1] *= a0;
                of[mi][ni][2] *= a1; of[mi][ni][3] *= a1;
            }
            int pr = (w * 32 + mi * 16 + gid) * PS_STRIDE;
            #pragma unroll
            for (int ni = 0; ni < 8; ni++) {
                float2 p0; p0.x = tf32r(sf[ni][0]); p0.y = tf32r(sf[ni][1]);
                *(float2*)(Ps + pr + ni * 8 + tig * 2) = p0;
                float2 p1; p1.x = tf32r(sf[ni][2]); p1.y = tf32r(sf[ni][3]);
                *(float2*)(Ps + pr + 8 * PS_STRIDE + ni * 8 + tig * 2) = p1;
            }
        }
        __syncwarp();

        #pragma unroll
        for (int ks = 0; ks < 8; ks++) {
            uint32_t pf[2][4];
            #pragma unroll
            for (int mi = 0; mi < 2; mi++) {
                int r = (w * 32 + mi * 16 + gid) * PS_STRIDE;
                pf[mi][0] = __float_as_uint(Ps[r + ks * 8 + tig]);
                pf[mi][1] = __float_as_uint(Ps[r + 8 * PS_STRIDE + ks * 8 + tig]);
                pf[mi][2] = __float_as_uint(Ps[r + ks * 8 + tig + 4]);
                pf[mi][3] = __float_as_uint(Ps[r + 8 * PS_STRIDE + ks * 8 + tig + 4]);
            }
            #pragma unroll
            for (int ni = 0; ni < 8; ni++) {
                uint32_t bfr[2];
                bfr[0] = __float_as_uint(Vs[(ks * 8 + tig) * VS_STRIDE + ni * 8 + gid]);
                bfr[1] = __float_as_uint(Vs[(ks * 8 + tig + 4) * VS_STRIDE + ni * 8 + gid]);
                mma_m16n8k8(of[0][ni], pf[0], bfr);
                mma_m16n8k8(of[1][ni], pf[1], bfr);
            }
        }
        __syncthreads();
    }

    #pragma unroll
    for (int mi = 0; mi < 2; mi++) {
        int r = q0 + w * 32 + mi * 16 + gid;
        float i0 = 1.0f / lrow[mi][0];
        float i1 = 1.0f / lrow[mi][1];
        #pragma unroll
        for (int ni = 0; ni < 8; ni++) {
            int cc = hoff + ni * 8 + tig * 2;
            float2 o0; o0.x = of[mi][ni][0] * i0; o0.y = of[mi][ni][1] * i0;
            *(float2*)(out + (size_t)r * DM + cc) = o0;
            float2 o1; o1.x = of[mi][ni][2] * i1; o1.y = of[mi][ni][3] * i1;
            *(float2*)(out + (size_t)(r + 8) * DM + cc) = o1;
        }
    }
}

// ---------------- host launch ----------------
extern "C" void kernel_launch(void* const* d_in, const int* in_sizes, int n_in,
                              void* d_out, int out_size) {
    const float* x    = (const float*)d_in[0];
    const float* cosp = (const float*)d_in[1];
    const float* sinp = (const float*)d_in[2];
    const float* wq   = (const float*)d_in[3];
    const float* wk   = (const float*)d_in[4];
    const float* wv   = (const float*)d_in[5];
    const float* wo   = (const float*)d_in[6];
    const float* w1   = (const float*)d_in[7];
    const float* w2   = (const float*)d_in[8];
    const float* w3   = (const float*)d_in[9];
    const float* anw  = (const float*)d_in[10];
    const float* fnw  = (const float*)d_in[11];

    float *hin, *q, *k, *v, *attn, *h, *f, *g1, *gate;
    cudaGetSymbolAddress((void**)&hin,  g_hin);
    cudaGetSymbolAddress((void**)&q,    g_q);
    cudaGetSymbolAddress((void**)&k,    g_k);
    cudaGetSymbolAddress((void**)&v,    g_v);
    cudaGetSymbolAddress((void**)&attn, g_attn);
    cudaGetSymbolAddress((void**)&h,    g_h);
    cudaGetSymbolAddress((void**)&f,    g_f);
    cudaGetSymbolAddress((void**)&g1,   g_g1);
    cudaGetSymbolAddress((void**)&gate, g_gate);

    float* out = (float*)d_out;

    const int ATTN_SMEM = (ATQ * PS_STRIDE + 64 * KS_STRIDE + 64 * VS_STRIDE) * 4;
    cudaFuncSetAttribute(attn_mma_kernel, cudaFuncAttributeMaxDynamicSharedMemorySize, ATTN_SMEM);

    // 1) attn rmsnorm
    rmsnorm_kernel<<<S_LEN, 256>>>(x, anw, hin);
    // 2) fused QKV projections (fp16 mma)
    gemm_mma_qkv<<<dim3(DM / 128, S_LEN / 128, 3), 256>>>(hin, wq, wk, wv, q, k, v, DM, DM);
    // 3) RoPE
    rope_kernel<<<(2 * S_LEN * NH * 32) / 256, 256>>>(q, k, cosp, sinp);
    // 4) attention (tensor-core flash, single wave)
    attn_mma_kernel<<<dim3(S_LEN / ATQ, NH), 256, ATTN_SMEM>>>(q, k, v, attn);
    // 5) output projection + residual
    gemm_mma<1><<<dim3(DM / 128, S_LEN / 128), 256>>>(attn, wo, h, DM, DM, x);
    // 6) ffn rmsnorm
    rmsnorm_kernel<<<S_LEN, 256>>>(h, fnw, f);
    // 7) swiglu
    gemm_mma<2><<<dim3(DFFN / 128, S_LEN / 128), 256>>>(f, w1, g1, DFFN, DM, nullptr);
    gemm_mma<3><<<dim3(DFFN / 128, S_LEN / 128), 256>>>(f, w3, gate, DFFN, DM, g1);
    // 8) down projection + residual -> out
    gemm_mma<1><<<dim3(DM / 128, S_LEN / 128), 256>>>(gate, w2, out, DM, DFFN, h);
}

// round 10
// speedup vs baseline: 5.3742x; 1.3333x over previous
#include <cuda_runtime.h>
#include <cuda_fp16.h>
#include <math.h>
#include <stdint.h>

#define S_LEN 2048
#define DM    1024
#define NH    16
#define DH    64
#define DFFN  4096

// ---------------- scratch (static device globals: no allocation) ----------------
__device__ float g_hin [S_LEN*DM];
__device__ float g_q   [S_LEN*DM];
__device__ float g_k   [S_LEN*DM];
__device__ float g_v   [S_LEN*DM];
__device__ float g_attn[S_LEN*DM];
__device__ float g_h   [S_LEN*DM];
__device__ float g_f   [S_LEN*DM];
__device__ float g_g1  [S_LEN*DFFN];
__device__ float g_gate[S_LEN*DFFN];

// ---------------- helpers ----------------
__device__ __forceinline__ void mma_m16n8k16h(float* d, const uint32_t* a, const uint32_t* b) {
    asm volatile("mma.sync.aligned.m16n8k16.row.col.f32.f16.f16.f32 "
                 "{%0,%1,%2,%3}, {%4,%5,%6,%7}, {%8,%9}, {%0,%1,%2,%3};"
                 : "+f"(d[0]), "+f"(d[1]), "+f"(d[2]), "+f"(d[3])
                 : "r"(a[0]), "r"(a[1]), "r"(a[2]), "r"(a[3]),
                   "r"(b[0]), "r"(b[1]));
}

__device__ __forceinline__ void ldsm_x4(uint32_t* r, uint32_t a) {
    asm volatile("ldmatrix.sync.aligned.m8n8.x4.shared.b16 {%0,%1,%2,%3}, [%4];"
                 : "=r"(r[0]), "=r"(r[1]), "=r"(r[2]), "=r"(r[3]) : "r"(a));
}
__device__ __forceinline__ void ldsm_x2(uint32_t* r, uint32_t a) {
    asm volatile("ldmatrix.sync.aligned.m8n8.x2.shared.b16 {%0,%1}, [%2];"
                 : "=r"(r[0]), "=r"(r[1]) : "r"(a));
}

__device__ __forceinline__ uint2 f4_to_h4(float4 v) {
    __half2 a = __floats2half2_rn(v.x, v.y);
    __half2 b = __floats2half2_rn(v.z, v.w);
    uint2 r;
    r.x = *(uint32_t*)&a;
    r.y = *(uint32_t*)&b;
    return r;
}
__device__ __forceinline__ uint32_t f2_to_u32(float x, float y) {
    __half2 h = __floats2half2_rn(x, y);
    return *(uint32_t*)&h;
}

// fused store of 2 adjacent outputs
template <int EPI>
__device__ __forceinline__ void store2(float* __restrict__ C, const float* __restrict__ R,
                                       size_t idx, float x, float y) {
    if (EPI == 1) {
        float2 r = *(const float2*)(R + idx);
        x += r.x; y += r.y;
    } else if (EPI == 2) {
        x = x / (1.0f + expf(-x));
        y = y / (1.0f + expf(-y));
    } else if (EPI == 3) {
        float2 r = *(const float2*)(R + idx);
        x *= r.x; y *= r.y;
    }
    float2 o; o.x = x; o.y = y;
    *(float2*)(C + idx) = o;
}

// ---------------- fp16 m16n8k16 GEMM, double-buffered + ldmatrix ----------------
// C[M,N] = A[M,K] @ B[K,N] (row-major inputs), CTA 128x128, BK=32, 8 warps 64x32.
#define HS 40
#define ABUF (128 * HS)   // halves per buffer

template <int EPI>
__device__ __forceinline__ void gemm_mma_core(const float* __restrict__ A,
                                              const float* __restrict__ B,
                                              float* __restrict__ C,
                                              int N, int K,
                                              const float* __restrict__ R) {
    __shared__ __half As[2 * ABUF];
    __shared__ __half Bs[2 * ABUF];

    const int tid = threadIdx.x;
    const int w = tid >> 5, l = tid & 31;
    const int wm = (w >> 2) * 64;
    const int wn = (w & 3) * 32;
    const int gid = l >> 2, tig = l & 3;
    const int quad = l >> 3, lr = l & 7;
    const int m0 = blockIdx.y * 128, n0 = blockIdx.x * 128;
    const uint32_t asb = (uint32_t)__cvta_generic_to_shared(As);
    const uint32_t bsb = (uint32_t)__cvta_generic_to_shared(Bs);

    float acc[4][4][4];
    #pragma unroll
    for (int mi = 0; mi < 4; mi++)
        #pragma unroll
        for (int ni = 0; ni < 4; ni++)
            #pragma unroll
            for (int j = 0; j < 4; j++) acc[mi][ni][j] = 0.f;

    float4 pa[4];
    float  pb[4][4];
    // prefetch k-tile 0
    #pragma unroll
    for (int it = 0; it < 4; it++) {
        int f = tid + it * 256;
        pa[it] = *(const float4*)(A + (size_t)(m0 + (f >> 3)) * K + ((f & 7) << 2));
        int n = f & 127, kb = f >> 7;
        #pragma unroll
        for (int j = 0; j < 4; j++)
            pb[it][j] = B[(size_t)(4 * kb + j) * N + n0 + n];
    }
    // stage buffer 0
    #pragma unroll
    for (int it = 0; it < 4; it++) {
        int f = tid + it * 256;
        *(uint2*)(As + (f >> 3) * HS + ((f & 7) << 2)) = f4_to_h4(pa[it]);
        int n = f & 127, kb = f >> 7;
        float4 bv = make_float4(pb[it][0], pb[it][1], pb[it][2], pb[it][3]);
        *(uint2*)(Bs + n * HS + kb * 4) = f4_to_h4(bv);
    }
    __syncthreads();

    const int nkt = K >> 5;
    for (int kt = 0; kt < nkt; kt++) {
        const int p = kt & 1;
        const uint32_t aoff = asb + (uint32_t)p * (ABUF * 2);
        const uint32_t boff = bsb + (uint32_t)p * (ABUF * 2);

        // prefetch next k-tile to registers (overlaps compute)
        if (kt + 1 < nkt) {
            int k0 = (kt + 1) << 5;
            #pragma unroll
            for (int it = 0; it < 4; it++) {
                int f = tid + it * 256;
                pa[it] = *(const float4*)(A + (size_t)(m0 + (f >> 3)) * K + k0 + ((f & 7) << 2));
                int n = f & 127, kb = f >> 7;
                #pragma unroll
                for (int j = 0; j < 4; j++)
                    pb[it][j] = B[(size_t)(k0 + 4 * kb + j) * N + n0 + n];
            }
        }

        // compute from buffer p
        #pragma unroll
        for (int ks = 0; ks < 2; ks++) {
            uint32_t af[4][4];
            #pragma unroll
            for (int mi = 0; mi < 4; mi++) {
                int row = wm + mi * 16 + ((quad & 1) << 3) + lr;
                int col = ks * 16 + ((quad >> 1) << 3);
                ldsm_x4(af[mi], aoff + (uint32_t)(row * HS + col) * 2);
            }
            uint32_t bfr[4][2];
            #pragma unroll
            for (int ni = 0; ni < 4; ni++) {
                int row = wn + ni * 8 + lr;
                int col = ks * 16 + ((l >> 3) & 1) * 8;
                ldsm_x2(bfr[ni], boff + (uint32_t)(row * HS + col) * 2);
            }
            #pragma unroll
            for (int mi = 0; mi < 4; mi++)
                #pragma unroll
                for (int ni = 0; ni < 4; ni++)
                    mma_m16n8k16h(acc[mi][ni], af[mi], bfr[ni]);
        }

        // stage next tile into the other buffer
        if (kt + 1 < nkt) {
            __half* Ad = As + (1 - p) * ABUF;
            __half* Bd = Bs + (1 - p) * ABUF;
            #pragma unroll
            for (int it = 0; it < 4; it++) {
                int f = tid + it * 256;
                *(uint2*)(Ad + (f >> 3) * HS + ((f & 7) << 2)) = f4_to_h4(pa[it]);
                int n = f & 127, kb = f >> 7;
                float4 bv = make_float4(pb[it][0], pb[it][1], pb[it][2], pb[it][3]);
                *(uint2*)(Bd + n * HS + kb * 4) = f4_to_h4(bv);
            }
        }
        __syncthreads();
    }

    #pragma unroll
    for (int mi = 0; mi < 4; mi++) {
        #pragma unroll
        for (int ni = 0; ni < 4; ni++) {
            int r  = m0 + wm + mi * 16 + gid;
            int cc = n0 + wn + ni * 8 + 2 * tig;
            store2<EPI>(C, R, (size_t)r * N + cc,       acc[mi][ni][0], acc[mi][ni][1]);
            store2<EPI>(C, R, (size_t)(r + 8) * N + cc, acc[mi][ni][2], acc[mi][ni][3]);
        }
    }
}

template <int EPI>
__global__ void __launch_bounds__(256, 2) gemm_mma(const float* __restrict__ A,
                                                   const float* __restrict__ B,
                                                   float* __restrict__ C,
                                                   int N, int K,
                                                   const float* __restrict__ R) {
    gemm_mma_core<EPI>(A, B, C, N, K, R);
}

__global__ void __launch_bounds__(256, 2) gemm_mma_qkv(const float* __restrict__ A,
        const float* __restrict__ bq, const float* __restrict__ bk, const float* __restrict__ bv,
        float* __restrict__ q, float* __restrict__ k, float* __restrict__ v, int N, int K) {
    const float* B = blockIdx.z == 0 ? bq : (blockIdx.z == 1 ? bk : bv);
    float* C       = blockIdx.z == 0 ? q  : (blockIdx.z == 1 ? k  : v);
    gemm_mma_core<0>(A, B, C, N, K, nullptr);
}

// ---------------- RMSNorm ----------------
__global__ void __launch_bounds__(256) rmsnorm_kernel(const float* __restrict__ x,
                                                      const float* __restrict__ w,
                                                      float* __restrict__ out) {
    int row = blockIdx.x;
    int tid = threadIdx.x;
    const float4* xr = (const float4*)(x + (size_t)row * DM);
    const float4* wr = (const float4*)w;
    float4 v = xr[tid];
    float s = v.x*v.x + v.y*v.y + v.z*v.z + v.w*v.w;
    __shared__ float red[256];
    red[tid] = s;
    __syncthreads();
    for (int o = 128; o > 0; o >>= 1) {
        if (tid < o) red[tid] += red[tid + o];
        __syncthreads();
    }
    float inv = rsqrtf(red[0] * (1.0f / DM) + 1e-6f);
    float4 wv = wr[tid];
    float4 ov;
    ov.x = v.x * inv * wv.x;
    ov.y = v.y * inv * wv.y;
    ov.z = v.z * inv * wv.z;
    ov.w = v.w * inv * wv.w;
    ((float4*)(out + (size_t)row * DM))[tid] = ov;
}

// ---------------- fp16 flash attention (RoPE fused, in-register P) ----------------
// CTA: 256 q-rows x 1 head, 8 warps x 32 rows. Key tile 64.
#define ATQ 256
#define HST 72   // halves stride for Qs/Ks/Vs (frag banks 4*gid+tig: conflict-free)

__global__ void __launch_bounds__(256, 1) attn_mma_kernel(const float* __restrict__ q,
                                                          const float* __restrict__ k,
                                                          const float* __restrict__ v,
                                                          const float* __restrict__ cosp,
                                                          const float* __restrict__ sinp,
                                                          float* __restrict__ out) {
    extern __shared__ __half smh[];
    __half* Qs = smh;                 // 256 x 72 (transient)
    __half* Ks = smh;                 // 64 x 72 [key][d]
    __half* Vs = smh + 64 * HST;      // 64 x 72 [d][key] (transposed)

    const int tid = threadIdx.x;
    const int w = tid >> 5, l = tid & 31;
    const int gid = l >> 2, tig = l & 3;
    const int q0 = blockIdx.x * ATQ;
    const int head = blockIdx.y, hoff = head * DH;

    // stage Q: rope + 1/sqrt(64) scale + fp16
    #pragma unroll
    for (int it = 0; it < 16; it++) {
        int f = tid + it * 256;
        int row = f >> 4, c4 = f & 15;
        int s = q0 + row;
        float4 v4 = *(const float4*)(q + (size_t)s * DM + hoff + c4 * 4);
        int i0 = c4 * 2;
        float c0 = cosp[s * 32 + i0],     s0 = sinp[s * 32 + i0];
        float c1 = cosp[s * 32 + i0 + 1], s1 = sinp[s * 32 + i0 + 1];
        uint2 u;
        u.x = f2_to_u32((v4.x * c0 - v4.y * s0) * 0.125f,
                        (v4.x * s0 + v4.y * c0) * 0.125f);
        u.y = f2_to_u32((v4.z * c1 - v4.w * s1) * 0.125f,
                        (v4.z * s1 + v4.w * c1) * 0.125f);
        *(uint2*)(Qs + row * HST + c4 * 4) = u;
    }
    __syncthreads();

    // Q fragments (m16n8k16 A-frags), 4 k-groups of 16 over DH=64
    uint32_t qf[2][4][4];
    #pragma unroll
    for (int mi = 0; mi < 2; mi++) {
        int r = w * 32 + mi * 16 + gid;
        #pragma unroll
        for (int kg = 0; kg < 4; kg++) {
            qf[mi][kg][0] = *(const uint32_t*)(Qs + r * HST + kg * 16 + 2 * tig);
            qf[mi][kg][1] = *(const uint32_t*)(Qs + (r + 8) * HST + kg * 16 + 2 * tig);
            qf[mi][kg][2] = *(const uint32_t*)(Qs + r * HST + kg * 16 + 2 * tig + 8);
            qf[mi][kg][3] = *(const uint32_t*)(Qs + (r + 8) * HST + kg * 16 + 2 * tig + 8);
        }
    }
    __syncthreads();   // Qs region now reusable as Ks/Vs

    float of[2][8][4];
    float mrow[2][2], lrow[2][2];
    #pragma unroll
    for (int mi = 0; mi < 2; mi++) {
        mrow[mi][0] = -1e30f; mrow[mi][1] = -1e30f;
        lrow[mi][0] = 0.f;    lrow[mi][1] = 0.f;
        #pragma unroll
        for (int ni = 0; ni < 8; ni++)
            #pragma unroll
            for (int j = 0; j < 4; j++) of[mi][ni][j] = 0.f;
    }

    for (int k0 = 0; k0 < S_LEN; k0 += 64) {
        // stage K (rope) and V (transposed)
        #pragma unroll
        for (int it = 0; it < 4; it++) {
            int f = tid + it * 256;
            int row = f >> 4, c4 = f & 15;
            int s = k0 + row;
            float4 kv = *(const float4*)(k + (size_t)s * DM + hoff + c4 * 4);
            int i0 = c4 * 2;
            float c0 = cosp[s * 32 + i0],     s0 = sinp[s * 32 + i0];
            float c1 = cosp[s * 32 + i0 + 1], s1 = sinp[s * 32 + i0 + 1];
            uint2 u;
            u.x = f2_to_u32(kv.x * c0 - kv.y * s0, kv.x * s0 + kv.y * c0);
            u.y = f2_to_u32(kv.z * c1 - kv.w * s1, kv.z * s1 + kv.w * c1);
            *(uint2*)(Ks + row * HST + c4 * 4) = u;
            float4 vv = *(const float4*)(v + (size_t)s * DM + hoff + c4 * 4);
            Vs[(c4 * 4 + 0) * HST + row] = __float2half_rn(vv.x);
            Vs[(c4 * 4 + 1) * HST + row] = __float2half_rn(vv.y);
            Vs[(c4 * 4 + 2) * HST + row] = __float2half_rn(vv.z);
            Vs[(c4 * 4 + 3) * HST + row] = __float2half_rn(vv.w);
        }
        __syncthreads();

        #pragma unroll
        for (int mi = 0; mi < 2; mi++) {
            // S = Q K^T (16 x 64)
            float sf[8][4];
            #pragma unroll
            for (int ni = 0; ni < 8; ni++)
                #pragma unroll
                for (int j = 0; j < 4; j++) sf[ni][j] = 0.f;
            #pragma unroll
            for (int kg = 0; kg < 4; kg++) {
                #pragma unroll
                for (int ni = 0; ni < 8; ni++) {
                    uint32_t bfr[2];
                    bfr[0] = *(const uint32_t*)(Ks + (ni * 8 + gid) * HST + kg * 16 + 2 * tig);
                    bfr[1] = *(const uint32_t*)(Ks + (ni * 8 + gid) * HST + kg * 16 + 2 * tig + 8);
                    mma_m16n8k16h(sf[ni], qf[mi][kg], bfr);
                }
            }
            // online softmax (row stats in 4-lane groups)
            float mx0 = -1e30f, mx1 = -1e30f;
            #pragma unroll
            for (int ni = 0; ni < 8; ni++) {
                mx0 = fmaxf(mx0, fmaxf(sf[ni][0], sf[ni][1]));
                mx1 = fmaxf(mx1, fmaxf(sf[ni][2], sf[ni][3]));
            }
            mx0 = fmaxf(mx0, __shfl_xor_sync(0xffffffffu, mx0, 1, 4));
            mx0 = fmaxf(mx0, __shfl_xor_sync(0xffffffffu, mx0, 2, 4));
            mx1 = fmaxf(mx1, __shfl_xor_sync(0xffffffffu, mx1, 1, 4));
            mx1 = fmaxf(mx1, __shfl_xor_sync(0xffffffffu, mx1, 2, 4));
            float mn0 = fmaxf(mrow[mi][0], mx0);
            float mn1 = fmaxf(mrow[mi][1], mx1);
            float a0 = __expf(mrow[mi][0] - mn0);
            float a1 = __expf(mrow[mi][1] - mn1);
            float s0 = 0.f, s1 = 0.f;
            #pragma unroll
            for (int ni = 0; ni < 8; ni++) {
                sf[ni][0] = __expf(sf[ni][0] - mn0);
                sf[ni][1] = __expf(sf[ni][1] - mn0);
                sf[ni][2] = __expf(sf[ni][2] - mn1);
                sf[ni][3] = __expf(sf[ni][3] - mn1);
                s0 += sf[ni][0] + sf[ni][1];
                s1 += sf[ni][2] + sf[ni][3];
            }
            s0 += __shfl_xor_sync(0xffffffffu, s0, 1, 4);
            s0 += __shfl_xor_sync(0xffffffffu, s0, 2, 4);
            s1 += __shfl_xor_sync(0xffffffffu, s1, 1, 4);
            s1 += __shfl_xor_sync(0xffffffffu, s1, 2, 4);
            lrow[mi][0] = lrow[mi][0] * a0 + s0;
            lrow[mi][1] = lrow[mi][1] * a1 + s1;
            mrow[mi][0] = mn0; mrow[mi][1] = mn1;
            #pragma unroll
            for (int ni = 0; ni < 8; ni++) {
                of[mi][ni][0] *= a0; of[mi][ni][1] *= a0;
                of[mi][ni][2] *= a1; of[mi][ni][3] *= a1;
            }
            // O += P V : P c-frags convert directly to A-frags (no smem)
            #pragma unroll
            for (int kg = 0; kg < 4; kg++) {
                uint32_t pf[4];
                pf[0] = f2_to_u32(sf[2 * kg][0],     sf[2 * kg][1]);
                pf[1] = f2_to_u32(sf[2 * kg][2],     sf[2 * kg][3]);
                pf[2] = f2_to_u32(sf[2 * kg + 1][0], sf[2 * kg + 1][1]);
                pf[3] = f2_to_u32(sf[2 * kg + 1][2], sf[2 * kg + 1][3]);
                #pragma unroll
                for (int ni = 0; ni < 8; ni++) {
                    uint32_t bfr[2];
                    bfr[0] = *(const uint32_t*)(Vs + (ni * 8 + gid) * HST + kg * 16 + 2 * tig);
                    bfr[1] = *(const uint32_t*)(Vs + (ni * 8 + gid) * HST + kg * 16 + 2 * tig + 8);
                    mma_m16n8k16h(of[mi][ni], pf, bfr);
                }
            }
        }
        __syncthreads();
    }

    // normalize + store
    #pragma unroll
    for (int mi = 0; mi < 2; mi++) {
        int r = q0 + w * 32 + mi * 16 + gid;
        float i0 = 1.0f / lrow[mi][0];
        float i1 = 1.0f / lrow[mi][1];
        #pragma unroll
        for (int ni = 0; ni < 8; ni++) {
            int cc = hoff + ni * 8 + tig * 2;
            float2 o0; o0.x = of[mi][ni][0] * i0; o0.y = of[mi][ni][1] * i0;
            *(float2*)(out + (size_t)r * DM + cc) = o0;
            float2 o1; o1.x = of[mi][ni][2] * i1; o1.y = of[mi][ni][3] * i1;
            *(float2*)(out + (size_t)(r + 8) * DM + cc) = o1;
        }
    }
}

// ---------------- host launch ----------------
extern "C" void kernel_launch(void* const* d_in, const int* in_sizes, int n_in,
                              void* d_out, int out_size) {
    const float* x    = (const float*)d_in[0];
    const float* cosp = (const float*)d_in[1];
    const float* sinp = (const float*)d_in[2];
    const float* wq   = (const float*)d_in[3];
    const float* wk   = (const float*)d_in[4];
    const float* wv   = (const float*)d_in[5];
    const float* wo   = (const float*)d_in[6];
    const float* w1   = (const float*)d_in[7];
    const float* w2   = (const float*)d_in[8];
    const float* w3   = (const float*)d_in[9];
    const float* anw  = (const float*)d_in[10];
    const float* fnw  = (const float*)d_in[11];

    float *hin, *q, *k, *v, *attn, *h, *f, *g1, *gate;
    cudaGetSymbolAddress((void**)&hin,  g_hin);
    cudaGetSymbolAddress((void**)&q,    g_q);
    cudaGetSymbolAddress((void**)&k,    g_k);
    cudaGetSymbolAddress((void**)&v,    g_v);
    cudaGetSymbolAddress((void**)&attn, g_attn);
    cudaGetSymbolAddress((void**)&h,    g_h);
    cudaGetSymbolAddress((void**)&f,    g_f);
    cudaGetSymbolAddress((void**)&g1,   g_g1);
    cudaGetSymbolAddress((void**)&gate, g_gate);

    float* out = (float*)d_out;

    const int ATTN_SMEM = ATQ * HST * 2;   // 36864 bytes (Qs; Ks+Vs overlay is smaller)
    cudaFuncSetAttribute(attn_mma_kernel, cudaFuncAttributeMaxDynamicSharedMemorySize, ATTN_SMEM);

    // 1) attn rmsnorm
    rmsnorm_kernel<<<S_LEN, 256>>>(x, anw, hin);
    // 2) fused QKV projections (fp16 mma, double-buffered)
    gemm_mma_qkv<<<dim3(DM / 128, S_LEN / 128, 3), 256>>>(hin, wq, wk, wv, q, k, v, DM, DM);
    // 3) attention (fp16 flash, RoPE fused, in-register P)
    attn_mma_kernel<<<dim3(S_LEN / ATQ, NH), 256, ATTN_SMEM>>>(q, k, v, cosp, sinp, attn);
    // 4) output projection + residual
    gemm_mma<1><<<dim3(DM / 128, S_LEN / 128), 256>>>(attn, wo, h, DM, DM, x);
    // 5) ffn rmsnorm
    rmsnorm_kernel<<<S_LEN, 256>>>(h, fnw, f);
    // 6) swiglu
    gemm_mma<2><<<dim3(DFFN / 128, S_LEN / 128), 256>>>(f, w1, g1, DFFN, DM, nullptr);
    gemm_mma<3><<<dim3(DFFN / 128, S_LEN / 128), 256>>>(f, w3, gate, DFFN, DM, g1);
    // 7) down projection + residual -> out
    gemm_mma<1><<<dim3(DM / 128, S_LEN / 128), 256>>>(gate, w2, out, DM, DFFN, h);
}